// round 12
// baseline (speedup 1.0000x reference)
#include <cuda_runtime.h>
#include <cuda_fp16.h>
#include <cstdint>

// Fixed problem shapes (SimpleGCN): N=50000 nodes, E=800000 edges,
// layers 256->256 (h1), 256->128 (h2), 128->128 (h3), out = [N, 512] fp32.
#define MAXN 50000
#define MAXE 800000
#define MPAD 50048

// ---------------- device scratch (static allocation; no cudaMalloc) --------
__device__ __half g_hh[(size_t)MPAD * 256];   // GEMM output, fp16
__device__ __half g_a16[(size_t)MPAD * 256];  // GEMM A input, fp16 (x16 / agg out)
__device__ __half g_w1h[256 * 256], g_w1l[256 * 256];  // W1^T hi/lo [n][k]
__device__ __half g_w2h[128 * 256], g_w2l[128 * 256];  // W2^T hi/lo
__device__ __half g_w3h[128 * 128], g_w3l[128 * 128];  // W3^T hi/lo
__device__ float g_dinv[MAXN];
__device__ int   g_cnt[MAXN];     // INVARIANT: zero at call entry (restored by scatter)
__device__ int   g_offs[MAXN + 1];
__device__ int   g_bsum[64];
__device__ int2  g_edge[MAXE];    // packed (src, norm-as-int) per edge

// ---------------- edge dtype probe (per-thread, no global flag) --------------
__device__ __forceinline__ bool probe64(const int* __restrict__ ei32) {
    int acc = 0;
#pragma unroll
    for (int i = 1; i < 32; i += 2) acc |= ei32[i];
    return acc == 0;
}
__device__ __forceinline__ int load_edge(const int* __restrict__ p32,
                                         const long long* __restrict__ p64,
                                         bool is64, int e, int n) {
    int v = is64 ? (int)p64[e] : p32[e];
    v = v < 0 ? 0 : (v >= n ? n - 1 : v);
    return v;
}

// ---------------- kernel 1: fused prep (count || x->fp16 || W splits) --------
__global__ void k_prep(const float* __restrict__ x,
                       const float* __restrict__ W1,
                       const float* __restrict__ W2,
                       const float* __restrict__ W3,
                       const int* __restrict__ ei32,
                       const long long* __restrict__ ei64, int E, int n) {
    const int CB = (E + 255) >> 8;
    const int XB = (MPAD * 32) >> 8;
    const int W1E = 256 * 256, W2E = 128 * 256, W3E = 128 * 128;
    const int b = blockIdx.x, t = threadIdx.x;

    if (b < CB) {                            // --- degree histogram ---
        int e = b * 256 + t;
        if (e < E) {
            bool is64 = probe64(ei32);
            int d = load_edge(ei32, ei64, is64, E + e, n);
            atomicAdd(&g_cnt[d], 1);
        }
    } else if (b < CB + XB) {                // --- x -> fp16 (8 elems/thread) ---
        int i = (b - CB) * 256 + t;
        int row = i >> 5, q = i & 31;
        uint4 hv = make_uint4(0, 0, 0, 0);
        if (row < n) {
            const float* p = &x[(size_t)row * 256 + q * 8];
            float4 f0 = *(const float4*)p;
            float4 f1 = *(const float4*)(p + 4);
            __half2 p0 = __floats2half2_rn(f0.x, f0.y);
            __half2 p1 = __floats2half2_rn(f0.z, f0.w);
            __half2 p2 = __floats2half2_rn(f1.x, f1.y);
            __half2 p3 = __floats2half2_rn(f1.z, f1.w);
            hv.x = *(uint32_t*)&p0; hv.y = *(uint32_t*)&p1;
            hv.z = *(uint32_t*)&p2; hv.w = *(uint32_t*)&p3;
        }
        *(uint4*)&g_a16[(size_t)row * 256 + q * 8] = hv;
    } else {                                 // --- W^T hi/lo splits, 3 layers ---
        int i = (b - CB - XB) * 256 + t;
        const float* W; __half *dh, *dl; int K, N;
        if (i < W1E)             { W = W1; dh = g_w1h; dl = g_w1l; K = 256; N = 256; }
        else if (i < W1E + W2E)  { i -= W1E; W = W2; dh = g_w2h; dl = g_w2l; K = 256; N = 128; }
        else if (i < W1E + W2E + W3E) { i -= W1E + W2E; W = W3; dh = g_w3h; dl = g_w3l; K = 128; N = 128; }
        else return;
        int nn = i / K, kk = i - nn * K;
        float v = W[(size_t)kk * N + nn];
        __half h = __float2half_rn(v);
        __half l = __float2half_rn(v - __half2float(h));
        dh[i] = h;
        dl[i] = l;
    }
}

// ---------------- kernel 2: block scan of degrees + dinv ---------------------
__global__ void k_scan_dinv(int n) {
    __shared__ int ws[32];
    int i = blockIdx.x * 1024 + threadIdx.x;
    int v = (i < n) ? g_cnt[i] : 0;
    if (i < n) g_dinv[i] = rsqrtf((float)(v + 1));  // +1 self-loop

    int lane = threadIdx.x & 31, w = threadIdx.x >> 5;
    int xs = v;
#pragma unroll
    for (int d = 1; d < 32; d <<= 1) {
        int tt = __shfl_up_sync(0xFFFFFFFFu, xs, d);
        if (lane >= d) xs += tt;
    }
    if (lane == 31) ws[w] = xs;
    __syncthreads();
    if (w == 0) {
        int y = ws[lane];
#pragma unroll
        for (int d = 1; d < 32; d <<= 1) {
            int tt = __shfl_up_sync(0xFFFFFFFFu, y, d);
            if (lane >= d) y += tt;
        }
        ws[lane] = y;
    }
    __syncthreads();
    int ex = (w ? ws[w - 1] : 0) + xs - v;
    if (i < n) g_offs[i] = ex;
    if (threadIdx.x == 1023) g_bsum[blockIdx.x] = ws[31];
}

// ---------------- kernel 3: add block prefixes --------------------------------
__global__ void k_scan_add(int n) {
    __shared__ int sv[64];
    __shared__ int pref;
    int t = threadIdx.x;
    if (t < 64) sv[t] = (t < blockIdx.x) ? g_bsum[t] : 0;
    __syncthreads();
    if (t == 0) {
        int s = 0;
#pragma unroll
        for (int j = 0; j < 64; j++) s += sv[j];
        pref = s;
    }
    __syncthreads();
    int i = blockIdx.x * 1024 + t;
    if (i < n) g_offs[i] += pref;
}

// ---------------- kernel 4: scatter, 2 edges/thread (+ g_cnt re-zero) --------
// After this, g_offs[d] = END of node d; beg = d ? g_offs[d-1] : 0.
__global__ void k_scatter(const int* __restrict__ ei32,
                          const long long* __restrict__ ei64, int E, int n) {
    int i = blockIdx.x * blockDim.x + threadIdx.x;
    if (i < n) g_cnt[i] = 0;                 // invariant for next call
    int e0 = i * 2;
    if (e0 >= E) return;
    bool is64 = probe64(ei32);
    bool has1 = (e0 + 1) < E;

    int s0 = load_edge(ei32, ei64, is64, e0, n);
    int d0 = load_edge(ei32, ei64, is64, E + e0, n);
    int s1 = 0, d1 = 0;
    if (has1) {
        s1 = load_edge(ei32, ei64, is64, e0 + 1, n);
        d1 = load_edge(ei32, ei64, is64, E + e0 + 1, n);
    }
    // both atomics in flight before either dependent store
    int pos0 = atomicAdd(&g_offs[d0], 1);
    int pos1 = has1 ? atomicAdd(&g_offs[d1], 1) : 0;
    float w0 = g_dinv[s0] * g_dinv[d0];
    if (pos0 >= 0 && pos0 < MAXE) g_edge[pos0] = make_int2(s0, __float_as_int(w0));
    if (has1) {
        float w1 = g_dinv[s1] * g_dinv[d1];
        if (pos1 >= 0 && pos1 < MAXE) g_edge[pos1] = make_int2(s1, __float_as_int(w1));
    }
}

// ---------------- fp16 2-term warp-MMA GEMM (cp.async + ldmatrix) -----------
#define ROWW 20
#define ARR_B  (128 * ROWW * 4)
#define BUF_B2 (ARR_B * 3)

__device__ __forceinline__ void mma_f16(float* c, uint32_t a0, uint32_t a1,
                                        uint32_t a2, uint32_t a3,
                                        uint32_t b0, uint32_t b1) {
    asm volatile(
        "mma.sync.aligned.m16n8k16.row.col.f32.f16.f16.f32 "
        "{%0,%1,%2,%3}, {%4,%5,%6,%7}, {%8,%9}, {%0,%1,%2,%3};"
        : "+f"(c[0]), "+f"(c[1]), "+f"(c[2]), "+f"(c[3])
        : "r"(a0), "r"(a1), "r"(a2), "r"(a3), "r"(b0), "r"(b1));
}
__device__ __forceinline__ void ldsm_x4(uint32_t& r0, uint32_t& r1,
                                        uint32_t& r2, uint32_t& r3, uint32_t a) {
    asm volatile("ldmatrix.sync.aligned.m8n8.x4.shared.b16 {%0,%1,%2,%3}, [%4];"
                 : "=r"(r0), "=r"(r1), "=r"(r2), "=r"(r3) : "r"(a));
}
__device__ __forceinline__ void ldsm_x2(uint32_t& r0, uint32_t& r1, uint32_t a) {
    asm volatile("ldmatrix.sync.aligned.m8n8.x2.shared.b16 {%0,%1}, [%2];"
                 : "=r"(r0), "=r"(r1) : "r"(a));
}
__device__ __forceinline__ void cp16(uint32_t dst, const void* src) {
    asm volatile("cp.async.cg.shared.global [%0], [%1], 16;"
                 :: "r"(dst), "l"(src));
}
__device__ __forceinline__ uint32_t smem_u32(const void* p) {
    uint32_t a;
    asm("{ .reg .u64 t; cvta.to.shared.u64 t, %1; cvt.u32.u64 %0, t; }"
        : "=r"(a) : "l"(p));
    return a;
}

__global__ void __launch_bounds__(256, 2)
k_gemm_f16(int layer, int M, int K, int N) {
    extern __shared__ char smem[];
    const uint32_t sbase = smem_u32(smem);
    const __half* A  = g_a16;               // device-side binding; lda = 256
    const __half* Bh = (layer == 0) ? g_w1h : (layer == 1) ? g_w2h : g_w3h;
    const __half* Bl = (layer == 0) ? g_w1l : (layer == 1) ? g_w2l : g_w3l;
    const int lda = 256;

    const int tid  = threadIdx.x;
    const int lane = tid & 31;
    const int wid  = tid >> 5;
    const int wm   = wid & 1;
    const int wn   = wid >> 1;
    const int bm   = blockIdx.x * 128;
    const int bn   = blockIdx.y * 128;

    const int l4 = lane >> 2;
    const int l2 = (lane & 3) * 2;

    // ldmatrix per-lane address offsets (bytes)
    const uint32_t aLane = ((lane & 15) * ROWW + (lane >> 4) * 4) * 4;
    const uint32_t bLane = ((lane & 7) * ROWW + ((lane >> 3) & 1) * 4) * 4;

    float acc[4][4][4];
#pragma unroll
    for (int i = 0; i < 4; i++)
#pragma unroll
        for (int j = 0; j < 4; j++)
#pragma unroll
            for (int k = 0; k < 4; k++) acc[i][j][k] = 0.f;

    const int c0r = tid >> 2, c0q = tid & 3;
    const int nStages = K >> 5;

    auto issue = [&](int st, int buf) {
        const int k0 = st << 5;
        const uint32_t db = sbase + buf * BUF_B2;
        const uint32_t w0 = (c0r * ROWW + c0q * 4) * 4;
        const uint32_t w1 = ((c0r + 64) * ROWW + c0q * 4) * 4;
        const size_t a0 = (size_t)(bm + c0r) * lda + k0 + c0q * 8;
        const size_t a1 = (size_t)(bm + c0r + 64) * lda + k0 + c0q * 8;
        cp16(db + w0, A + a0);
        cp16(db + w1, A + a1);
        const size_t g0 = (size_t)(bn + c0r) * K + k0 + c0q * 8;
        const size_t g1 = (size_t)(bn + c0r + 64) * K + k0 + c0q * 8;
        cp16(db + ARR_B + w0, Bh + g0);
        cp16(db + ARR_B + w1, Bh + g1);
        cp16(db + 2 * ARR_B + w0, Bl + g0);
        cp16(db + 2 * ARR_B + w1, Bl + g1);
        asm volatile("cp.async.commit_group;");
    };

    issue(0, 0);

    for (int st = 0; st < nStages; st++) {
        const int buf = st & 1;
        if (st + 1 < nStages) {
            issue(st + 1, buf ^ 1);
            asm volatile("cp.async.wait_group 1;");
        } else {
            asm volatile("cp.async.wait_group 0;");
        }
        __syncthreads();

        const uint32_t sAaddr  = sbase + buf * BUF_B2;
        const uint32_t sBhaddr = sAaddr + ARR_B;
        const uint32_t sBladdr = sAaddr + 2 * ARR_B;

#pragma unroll
        for (int ks = 0; ks < 2; ks++) {
            const uint32_t ko = ks * 8 * 4;   // k word offset in bytes
            uint32_t bh[4][2], bl[4][2];
#pragma unroll
            for (int nt = 0; nt < 4; nt++) {
                uint32_t nb = (uint32_t)((wn * 32 + nt * 8) * ROWW) * 4 + ko + bLane;
                ldsm_x2(bh[nt][0], bh[nt][1], sBhaddr + nb);
                ldsm_x2(bl[nt][0], bl[nt][1], sBladdr + nb);
            }
#pragma unroll
            for (int mt = 0; mt < 4; mt++) {
                uint32_t ma = (uint32_t)((wm * 64 + mt * 16) * ROWW) * 4 + ko + aLane;
                uint32_t a0, a1, a2, a3;
                ldsm_x4(a0, a1, a2, a3, sAaddr + ma);
#pragma unroll
                for (int nt = 0; nt < 4; nt++)
                    mma_f16(acc[mt][nt], a0, a1, a2, a3, bh[nt][0], bh[nt][1]);
#pragma unroll
                for (int nt = 0; nt < 4; nt++)
                    mma_f16(acc[mt][nt], a0, a1, a2, a3, bl[nt][0], bl[nt][1]);
            }
        }
        __syncthreads();
    }

#pragma unroll
    for (int mt = 0; mt < 4; mt++) {
#pragma unroll
        for (int nt = 0; nt < 4; nt++) {
            int row = bm + wm * 64 + mt * 16 + l4;
            int col = bn + wn * 32 + nt * 8 + l2;
            if (row < M)
                *(__half2*)&g_hh[(size_t)row * N + col] =
                    __floats2half2_rn(acc[mt][nt][0], acc[mt][nt][1]);
            if (row + 8 < M)
                *(__half2*)&g_hh[(size_t)(row + 8) * N + col] =
                    __floats2half2_rn(acc[mt][nt][2], acc[mt][nt][3]);
        }
    }
}

// ---------------- aggregation (fp16 gathers, packed edges) -------------------
__device__ __forceinline__ void unpack8(uint4 v, float* f) {
    float2 a = __half22float2(*(__half2*)&v.x);
    float2 b = __half22float2(*(__half2*)&v.y);
    float2 c = __half22float2(*(__half2*)&v.z);
    float2 d = __half22float2(*(__half2*)&v.w);
    f[0] = a.x; f[1] = a.y; f[2] = b.x; f[3] = b.y;
    f[4] = c.x; f[5] = c.y; f[6] = d.x; f[7] = d.y;
}

// NPB nodes per block; OC/8 threads per node. W16: also write fp16 copy to g_a16.
// g_offs holds END positions (post-scatter); beg = node ? offs[node-1] : 0.
template <int OC, int NPB, bool W16>
__global__ void k_agg(const float* __restrict__ bias,
                      float* __restrict__ out, int ldo, int n) {
    int node = blockIdx.x * NPB + threadIdx.y;
    if (node >= n) return;
    const int colb = threadIdx.x * 8;

    float di = g_dinv[node];
    float s2 = di * di;

    float acc[8], f[8];
    uint4 hs = *(const uint4*)&g_hh[(size_t)node * OC + colb];
    unpack8(hs, f);
#pragma unroll
    for (int j = 0; j < 8; j++) acc[j] = f[j] * s2;

    int beg = node ? g_offs[node - 1] : 0;
    int end = g_offs[node];
    int e = beg;
    for (; e + 1 < end; e += 2) {
        int2 ed0 = g_edge[e], ed1 = g_edge[e + 1];
        float w0 = __int_as_float(ed0.y), w1 = __int_as_float(ed1.y);
        uint4 v0 = *(const uint4*)&g_hh[(size_t)ed0.x * OC + colb];
        uint4 v1 = *(const uint4*)&g_hh[(size_t)ed1.x * OC + colb];
        float f0[8], f1[8];
        unpack8(v0, f0);
        unpack8(v1, f1);
#pragma unroll
        for (int j = 0; j < 8; j++) acc[j] += f0[j] * w0 + f1[j] * w1;
    }
    if (e < end) {
        int2 ed = g_edge[e];
        float w = __int_as_float(ed.y);
        uint4 v = *(const uint4*)&g_hh[(size_t)ed.x * OC + colb];
        unpack8(v, f);
#pragma unroll
        for (int j = 0; j < 8; j++) acc[j] += f[j] * w;
    }

    float4 b0 = *(const float4*)&bias[colb];
    float4 b1 = *(const float4*)&bias[colb + 4];
    float r[8];
    r[0] = fmaxf(acc[0] + b0.x, 0.f); r[1] = fmaxf(acc[1] + b0.y, 0.f);
    r[2] = fmaxf(acc[2] + b0.z, 0.f); r[3] = fmaxf(acc[3] + b0.w, 0.f);
    r[4] = fmaxf(acc[4] + b1.x, 0.f); r[5] = fmaxf(acc[5] + b1.y, 0.f);
    r[6] = fmaxf(acc[6] + b1.z, 0.f); r[7] = fmaxf(acc[7] + b1.w, 0.f);

    float* op = &out[(size_t)node * ldo + colb];
    *(float4*)op       = make_float4(r[0], r[1], r[2], r[3]);
    *(float4*)(op + 4) = make_float4(r[4], r[5], r[6], r[7]);

    if (W16) {
        uint4 hv;
        __half2 p0 = __floats2half2_rn(r[0], r[1]);
        __half2 p1 = __floats2half2_rn(r[2], r[3]);
        __half2 p2 = __floats2half2_rn(r[4], r[5]);
        __half2 p3 = __floats2half2_rn(r[6], r[7]);
        hv.x = *(uint32_t*)&p0; hv.y = *(uint32_t*)&p1;
        hv.z = *(uint32_t*)&p2; hv.w = *(uint32_t*)&p3;
        *(uint4*)&g_a16[(size_t)node * 256 + colb] = hv;
    }
}

// ---------------- host launcher ----------------------------------------------
extern "C" void kernel_launch(void* const* d_in, const int* in_sizes, int n_in,
                              void* d_out, int out_size) {
    const float* x  = (const float*)d_in[0];
    const int*       ei32 = (const int*)d_in[1];
    const long long* ei64 = (const long long*)d_in[1];
    const float* W1 = (const float*)d_in[2];
    const float* b1 = (const float*)d_in[3];
    const float* W2 = (const float*)d_in[4];
    const float* b2 = (const float*)d_in[5];
    const float* W3 = (const float*)d_in[6];
    const float* b3 = (const float*)d_in[7];
    float* out = (float*)d_out;

    int n = in_sizes[0] / 256;   // 50000
    int E = in_sizes[1] / 2;     // 800000

    const int SMEM2 = 2 * BUF_B2;  // 61440
    cudaFuncSetAttribute(k_gemm_f16,
                         cudaFuncAttributeMaxDynamicSharedMemorySize, SMEM2);

    const int CB = (E + 255) / 256;
    const int XB = (MPAD * 32) / 256;
    const int WB = (256 * 256 + 128 * 256 + 128 * 128 + 255) / 256;
    k_prep<<<CB + XB + WB, 256>>>(x, W1, W2, W3, ei32, ei64, E, n);

    int nb = (n + 1023) / 1024;  // 49
    k_scan_dinv<<<nb, 1024>>>(n);
    k_scan_add<<<nb, 1024>>>(n);
    k_scatter<<<(E / 2 + 255) / 256, 256>>>(ei32, ei64, E, n);

    const int mtiles = (n + 127) / 128;  // 391

    // --- layer 1: 256 -> 256 ---
    k_gemm_f16<<<dim3(mtiles, 2), 256, SMEM2>>>(0, n, 256, 256);
    k_agg<256, 8, true><<<(n + 7) / 8, dim3(32, 8)>>>(b1, out, 512, n);

    // --- layer 2: 256 -> 128 ---
    k_gemm_f16<<<dim3(mtiles, 1), 256, SMEM2>>>(1, n, 256, 128);
    k_agg<128, 16, true><<<(n + 15) / 16, dim3(16, 16)>>>(b2, out + 256, 512, n);

    // --- layer 3: 128 -> 128 ---
    k_gemm_f16<<<dim3(mtiles, 1), 256, SMEM2>>>(2, n, 128, 128);
    k_agg<128, 16, false><<<(n + 15) / 16, dim3(16, 16)>>>(b3, out + 384, 512, n);
}

// round 13
// speedup vs baseline: 1.1328x; 1.1328x over previous
#include <cuda_runtime.h>
#include <cuda_fp16.h>
#include <cstdint>

// Fixed problem shapes (SimpleGCN): N=50000 nodes, E=800000 edges,
// layers 256->256 (h1), 256->128 (h2), 128->128 (h3), out = [N, 512] fp32.
#define MAXN 50000
#define MAXE 800000
#define MPAD 50048

// ---------------- device scratch (static allocation; no cudaMalloc) --------
__device__ __half g_hh[(size_t)MPAD * 256];   // GEMM output, fp16
__device__ __half g_a16[(size_t)MPAD * 256];  // GEMM A input, fp16 (x16 / agg out)
__device__ __half g_w1h[256 * 256];           // W1^T fp16 [n][k]
__device__ __half g_w2h[128 * 256];           // W2^T fp16
__device__ __half g_w3h[128 * 128];           // W3^T fp16
__device__ float g_dinv[MAXN];
__device__ int   g_cnt[MAXN];     // INVARIANT: zero at call entry (restored by scatter)
__device__ int   g_offs[MAXN + 1];
__device__ int   g_bsum[64];
__device__ int2  g_edge[MAXE];    // packed (src, norm-as-int) per edge

// ---------------- edge dtype probe (per-thread, no global flag) --------------
__device__ __forceinline__ bool probe64(const int* __restrict__ ei32) {
    int acc = 0;
#pragma unroll
    for (int i = 1; i < 32; i += 2) acc |= ei32[i];
    return acc == 0;
}
__device__ __forceinline__ int load_edge(const int* __restrict__ p32,
                                         const long long* __restrict__ p64,
                                         bool is64, int e, int n) {
    int v = is64 ? (int)p64[e] : p32[e];
    v = v < 0 ? 0 : (v >= n ? n - 1 : v);
    return v;
}

// ---------------- kernel 1: fused prep (count || x->fp16 || W^T fp16) --------
__global__ void k_prep(const float* __restrict__ x,
                       const float* __restrict__ W1,
                       const float* __restrict__ W2,
                       const float* __restrict__ W3,
                       const int* __restrict__ ei32,
                       const long long* __restrict__ ei64, int E, int n) {
    const int CB = (E + 255) >> 8;
    const int XB = (MPAD * 32) >> 8;
    const int W1E = 256 * 256, W2E = 128 * 256, W3E = 128 * 128;
    const int b = blockIdx.x, t = threadIdx.x;

    if (b < CB) {                            // --- degree histogram ---
        int e = b * 256 + t;
        if (e < E) {
            bool is64 = probe64(ei32);
            int d = load_edge(ei32, ei64, is64, E + e, n);
            atomicAdd(&g_cnt[d], 1);
        }
    } else if (b < CB + XB) {                // --- x -> fp16 (8 elems/thread) ---
        int i = (b - CB) * 256 + t;
        int row = i >> 5, q = i & 31;
        uint4 hv = make_uint4(0, 0, 0, 0);
        if (row < n) {
            const float* p = &x[(size_t)row * 256 + q * 8];
            float4 f0 = *(const float4*)p;
            float4 f1 = *(const float4*)(p + 4);
            __half2 p0 = __floats2half2_rn(f0.x, f0.y);
            __half2 p1 = __floats2half2_rn(f0.z, f0.w);
            __half2 p2 = __floats2half2_rn(f1.x, f1.y);
            __half2 p3 = __floats2half2_rn(f1.z, f1.w);
            hv.x = *(uint32_t*)&p0; hv.y = *(uint32_t*)&p1;
            hv.z = *(uint32_t*)&p2; hv.w = *(uint32_t*)&p3;
        }
        *(uint4*)&g_a16[(size_t)row * 256 + q * 8] = hv;
    } else {                                 // --- W^T fp16, 3 layers ---
        int i = (b - CB - XB) * 256 + t;
        const float* W; __half* dh; int K, N;
        if (i < W1E)             { W = W1; dh = g_w1h; K = 256; N = 256; }
        else if (i < W1E + W2E)  { i -= W1E; W = W2; dh = g_w2h; K = 256; N = 128; }
        else if (i < W1E + W2E + W3E) { i -= W1E + W2E; W = W3; dh = g_w3h; K = 128; N = 128; }
        else return;
        int nn = i / K, kk = i - nn * K;
        dh[i] = __float2half_rn(W[(size_t)kk * N + nn]);
    }
}

// ---------------- kernel 2: block scan of degrees + dinv ---------------------
__global__ void k_scan_dinv(int n) {
    __shared__ int ws[32];
    int i = blockIdx.x * 1024 + threadIdx.x;
    int v = (i < n) ? g_cnt[i] : 0;
    if (i < n) g_dinv[i] = rsqrtf((float)(v + 1));  // +1 self-loop

    int lane = threadIdx.x & 31, w = threadIdx.x >> 5;
    int xs = v;
#pragma unroll
    for (int d = 1; d < 32; d <<= 1) {
        int tt = __shfl_up_sync(0xFFFFFFFFu, xs, d);
        if (lane >= d) xs += tt;
    }
    if (lane == 31) ws[w] = xs;
    __syncthreads();
    if (w == 0) {
        int y = ws[lane];
#pragma unroll
        for (int d = 1; d < 32; d <<= 1) {
            int tt = __shfl_up_sync(0xFFFFFFFFu, y, d);
            if (lane >= d) y += tt;
        }
        ws[lane] = y;
    }
    __syncthreads();
    int ex = (w ? ws[w - 1] : 0) + xs - v;
    if (i < n) g_offs[i] = ex;
    if (threadIdx.x == 1023) g_bsum[blockIdx.x] = ws[31];
}

// ---------------- kernel 3: add block prefixes --------------------------------
__global__ void k_scan_add(int n) {
    __shared__ int sv[64];
    __shared__ int pref;
    int t = threadIdx.x;
    if (t < 64) sv[t] = (t < blockIdx.x) ? g_bsum[t] : 0;
    __syncthreads();
    if (t == 0) {
        int s = 0;
#pragma unroll
        for (int j = 0; j < 64; j++) s += sv[j];
        pref = s;
    }
    __syncthreads();
    int i = blockIdx.x * 1024 + t;
    if (i < n) g_offs[i] += pref;
}

// ---------------- kernel 4: scatter, 2 edges/thread (+ g_cnt re-zero) --------
// After this, g_offs[d] = END of node d; beg = d ? g_offs[d-1] : 0.
__global__ void k_scatter(const int* __restrict__ ei32,
                          const long long* __restrict__ ei64, int E, int n) {
    int i = blockIdx.x * blockDim.x + threadIdx.x;
    if (i < n) g_cnt[i] = 0;                 // invariant for next call
    int e0 = i * 2;
    if (e0 >= E) return;
    bool is64 = probe64(ei32);
    bool has1 = (e0 + 1) < E;

    int s0 = load_edge(ei32, ei64, is64, e0, n);
    int d0 = load_edge(ei32, ei64, is64, E + e0, n);
    int s1 = 0, d1 = 0;
    if (has1) {
        s1 = load_edge(ei32, ei64, is64, e0 + 1, n);
        d1 = load_edge(ei32, ei64, is64, E + e0 + 1, n);
    }
    int pos0 = atomicAdd(&g_offs[d0], 1);
    int pos1 = has1 ? atomicAdd(&g_offs[d1], 1) : 0;
    float w0 = g_dinv[s0] * g_dinv[d0];
    if (pos0 >= 0 && pos0 < MAXE) g_edge[pos0] = make_int2(s0, __float_as_int(w0));
    if (has1) {
        float w1 = g_dinv[s1] * g_dinv[d1];
        if (pos1 >= 0 && pos1 < MAXE) g_edge[pos1] = make_int2(s1, __float_as_int(w1));
    }
}

// ---------------- fp16 1-term warp-MMA GEMM (cp.async pipelined) -------------
// C[M,N] = g_a16[M,*256] @ W[K,N]; W^T fp16 selected by layer (device-side).
// CTA tile 128x128, 8 warps (2M x 4N), warp tile 64x32 via m16n8k16.
#define ROWW 20
#define ARR_B  (128 * ROWW * 4)
#define BUF_B1 (ARR_B * 2)

__device__ __forceinline__ void mma_f16(float* c, uint32_t a0, uint32_t a1,
                                        uint32_t a2, uint32_t a3,
                                        uint32_t b0, uint32_t b1) {
    asm volatile(
        "mma.sync.aligned.m16n8k16.row.col.f32.f16.f16.f32 "
        "{%0,%1,%2,%3}, {%4,%5,%6,%7}, {%8,%9}, {%0,%1,%2,%3};"
        : "+f"(c[0]), "+f"(c[1]), "+f"(c[2]), "+f"(c[3])
        : "r"(a0), "r"(a1), "r"(a2), "r"(a3), "r"(b0), "r"(b1));
}
__device__ __forceinline__ void cp16(uint32_t dst, const void* src) {
    asm volatile("cp.async.cg.shared.global [%0], [%1], 16;"
                 :: "r"(dst), "l"(src));
}
__device__ __forceinline__ uint32_t smem_u32(const void* p) {
    uint32_t a;
    asm("{ .reg .u64 t; cvta.to.shared.u64 t, %1; cvt.u32.u64 %0, t; }"
        : "=r"(a) : "l"(p));
    return a;
}

__global__ void __launch_bounds__(256, 2)
k_gemm_f16(int layer, int M, int K, int N) {
    extern __shared__ char smem[];
    const uint32_t sbase = smem_u32(smem);
    const __half* A  = g_a16;               // device-side binding; lda = 256
    const __half* Bh = (layer == 0) ? g_w1h : (layer == 1) ? g_w2h : g_w3h;
    const int lda = 256;

    const int tid  = threadIdx.x;
    const int lane = tid & 31;
    const int wid  = tid >> 5;
    const int wm   = wid & 1;
    const int wn   = wid >> 1;
    const int bm   = blockIdx.x * 128;
    const int bn   = blockIdx.y * 128;

    const int l4 = lane >> 2;
    const int l2 = (lane & 3) * 2;

    float acc[4][4][4];
#pragma unroll
    for (int i = 0; i < 4; i++)
#pragma unroll
        for (int j = 0; j < 4; j++)
#pragma unroll
            for (int k = 0; k < 4; k++) acc[i][j][k] = 0.f;

    const int c0r = tid >> 2, c0q = tid & 3;
    const int nStages = K >> 5;

    // A rows bm..bm+127 may exceed M but stay < MPAD (g_a16 padded): safe.
    auto issue = [&](int st, int buf) {
        const int k0 = st << 5;
        const uint32_t db = sbase + buf * BUF_B1;
        const uint32_t w0 = (c0r * ROWW + c0q * 4) * 4;
        const uint32_t w1 = ((c0r + 64) * ROWW + c0q * 4) * 4;
        const size_t a0 = (size_t)(bm + c0r) * lda + k0 + c0q * 8;
        const size_t a1 = (size_t)(bm + c0r + 64) * lda + k0 + c0q * 8;
        cp16(db + w0, A + a0);
        cp16(db + w1, A + a1);
        const size_t g0 = (size_t)(bn + c0r) * K + k0 + c0q * 8;
        const size_t g1 = (size_t)(bn + c0r + 64) * K + k0 + c0q * 8;
        cp16(db + ARR_B + w0, Bh + g0);
        cp16(db + ARR_B + w1, Bh + g1);
        asm volatile("cp.async.commit_group;");
    };

    issue(0, 0);

    for (int st = 0; st < nStages; st++) {
        const int buf = st & 1;
        if (st + 1 < nStages) {
            issue(st + 1, buf ^ 1);
            asm volatile("cp.async.wait_group 1;");
        } else {
            asm volatile("cp.async.wait_group 0;");
        }
        __syncthreads();

        const uint32_t* sA  = (const uint32_t*)(smem + buf * BUF_B1);
        const uint32_t* sBh = (const uint32_t*)(smem + buf * BUF_B1 + ARR_B);

#pragma unroll
        for (int ks = 0; ks < 2; ks++) {
            const int kwb = ks * 8 + (lane & 3);
            uint32_t bh[4][2];
#pragma unroll
            for (int nt = 0; nt < 4; nt++) {
                int rw = (wn * 32 + nt * 8 + l4) * ROWW + kwb;
                bh[nt][0] = sBh[rw]; bh[nt][1] = sBh[rw + 4];
            }
#pragma unroll
            for (int mt = 0; mt < 4; mt++) {
                int r0 = (wm * 64 + mt * 16 + l4) * ROWW + kwb;
                int r1 = r0 + 8 * ROWW;
                uint32_t a0 = sA[r0], a1 = sA[r1];
                uint32_t a2 = sA[r0 + 4], a3 = sA[r1 + 4];
#pragma unroll
                for (int nt = 0; nt < 4; nt++)
                    mma_f16(acc[mt][nt], a0, a1, a2, a3, bh[nt][0], bh[nt][1]);
            }
        }
        __syncthreads();
    }

#pragma unroll
    for (int mt = 0; mt < 4; mt++) {
#pragma unroll
        for (int nt = 0; nt < 4; nt++) {
            int row = bm + wm * 64 + mt * 16 + l4;
            int col = bn + wn * 32 + nt * 8 + l2;
            if (row < M)
                *(__half2*)&g_hh[(size_t)row * N + col] =
                    __floats2half2_rn(acc[mt][nt][0], acc[mt][nt][1]);
            if (row + 8 < M)
                *(__half2*)&g_hh[(size_t)(row + 8) * N + col] =
                    __floats2half2_rn(acc[mt][nt][2], acc[mt][nt][3]);
        }
    }
}

// ---------------- aggregation (fp16 gathers, packed edges) -------------------
__device__ __forceinline__ void unpack8(uint4 v, float* f) {
    float2 a = __half22float2(*(__half2*)&v.x);
    float2 b = __half22float2(*(__half2*)&v.y);
    float2 c = __half22float2(*(__half2*)&v.z);
    float2 d = __half22float2(*(__half2*)&v.w);
    f[0] = a.x; f[1] = a.y; f[2] = b.x; f[3] = b.y;
    f[4] = c.x; f[5] = c.y; f[6] = d.x; f[7] = d.y;
}

// NPB nodes per block; OC/8 threads per node. W16: also write fp16 copy to g_a16.
// g_offs holds END positions (post-scatter); beg = node ? offs[node-1] : 0.
template <int OC, int NPB, bool W16>
__global__ void k_agg(const float* __restrict__ bias,
                      float* __restrict__ out, int ldo, int n) {
    int node = blockIdx.x * NPB + threadIdx.y;
    if (node >= n) return;
    const int colb = threadIdx.x * 8;

    float di = g_dinv[node];
    float s2 = di * di;

    float acc[8], f[8];
    uint4 hs = *(const uint4*)&g_hh[(size_t)node * OC + colb];
    unpack8(hs, f);
#pragma unroll
    for (int j = 0; j < 8; j++) acc[j] = f[j] * s2;

    int beg = node ? g_offs[node - 1] : 0;
    int end = g_offs[node];
    int e = beg;
    for (; e + 1 < end; e += 2) {
        int2 ed0 = g_edge[e], ed1 = g_edge[e + 1];
        float w0 = __int_as_float(ed0.y), w1 = __int_as_float(ed1.y);
        uint4 v0 = *(const uint4*)&g_hh[(size_t)ed0.x * OC + colb];
        uint4 v1 = *(const uint4*)&g_hh[(size_t)ed1.x * OC + colb];
        float f0[8], f1[8];
        unpack8(v0, f0);
        unpack8(v1, f1);
#pragma unroll
        for (int j = 0; j < 8; j++) acc[j] += f0[j] * w0 + f1[j] * w1;
    }
    if (e < end) {
        int2 ed = g_edge[e];
        float w = __int_as_float(ed.y);
        uint4 v = *(const uint4*)&g_hh[(size_t)ed.x * OC + colb];
        unpack8(v, f);
#pragma unroll
        for (int j = 0; j < 8; j++) acc[j] += f[j] * w;
    }

    float4 b0 = *(const float4*)&bias[colb];
    float4 b1 = *(const float4*)&bias[colb + 4];
    float r[8];
    r[0] = fmaxf(acc[0] + b0.x, 0.f); r[1] = fmaxf(acc[1] + b0.y, 0.f);
    r[2] = fmaxf(acc[2] + b0.z, 0.f); r[3] = fmaxf(acc[3] + b0.w, 0.f);
    r[4] = fmaxf(acc[4] + b1.x, 0.f); r[5] = fmaxf(acc[5] + b1.y, 0.f);
    r[6] = fmaxf(acc[6] + b1.z, 0.f); r[7] = fmaxf(acc[7] + b1.w, 0.f);

    float* op = &out[(size_t)node * ldo + colb];
    *(float4*)op       = make_float4(r[0], r[1], r[2], r[3]);
    *(float4*)(op + 4) = make_float4(r[4], r[5], r[6], r[7]);

    if (W16) {
        uint4 hv;
        __half2 p0 = __floats2half2_rn(r[0], r[1]);
        __half2 p1 = __floats2half2_rn(r[2], r[3]);
        __half2 p2 = __floats2half2_rn(r[4], r[5]);
        __half2 p3 = __floats2half2_rn(r[6], r[7]);
        hv.x = *(uint32_t*)&p0; hv.y = *(uint32_t*)&p1;
        hv.z = *(uint32_t*)&p2; hv.w = *(uint32_t*)&p3;
        *(uint4*)&g_a16[(size_t)node * 256 + colb] = hv;
    }
}

// ---------------- host launcher ----------------------------------------------
extern "C" void kernel_launch(void* const* d_in, const int* in_sizes, int n_in,
                              void* d_out, int out_size) {
    const float* x  = (const float*)d_in[0];
    const int*       ei32 = (const int*)d_in[1];
    const long long* ei64 = (const long long*)d_in[1];
    const float* W1 = (const float*)d_in[2];
    const float* b1 = (const float*)d_in[3];
    const float* W2 = (const float*)d_in[4];
    const float* b2 = (const float*)d_in[5];
    const float* W3 = (const float*)d_in[6];
    const float* b3 = (const float*)d_in[7];
    float* out = (float*)d_out;

    int n = in_sizes[0] / 256;   // 50000
    int E = in_sizes[1] / 2;     // 800000

    const int SMEM1 = 2 * BUF_B1;  // 40960
    cudaFuncSetAttribute(k_gemm_f16,
                         cudaFuncAttributeMaxDynamicSharedMemorySize, SMEM1);

    const int CB = (E + 255) / 256;
    const int XB = (MPAD * 32) / 256;
    const int WB = (256 * 256 + 128 * 256 + 128 * 128 + 255) / 256;
    k_prep<<<CB + XB + WB, 256>>>(x, W1, W2, W3, ei32, ei64, E, n);

    int nb = (n + 1023) / 1024;  // 49
    k_scan_dinv<<<nb, 1024>>>(n);
    k_scan_add<<<nb, 1024>>>(n);
    k_scatter<<<(E / 2 + 255) / 256, 256>>>(ei32, ei64, E, n);

    const int mtiles = (n + 127) / 128;  // 391

    // --- layer 1: 256 -> 256 ---
    k_gemm_f16<<<dim3(mtiles, 2), 256, SMEM1>>>(0, n, 256, 256);
    k_agg<256, 8, true><<<(n + 7) / 8, dim3(32, 8)>>>(b1, out, 512, n);

    // --- layer 2: 256 -> 128 ---
    k_gemm_f16<<<dim3(mtiles, 1), 256, SMEM1>>>(1, n, 256, 128);
    k_agg<128, 16, true><<<(n + 15) / 16, dim3(16, 16)>>>(b2, out + 256, 512, n);

    // --- layer 3: 128 -> 128 ---
    k_gemm_f16<<<dim3(mtiles, 1), 256, SMEM1>>>(2, n, 128, 128);
    k_agg<128, 16, false><<<(n + 15) / 16, dim3(16, 16)>>>(b3, out + 384, 512, n);
}

// round 14
// speedup vs baseline: 1.1483x; 1.0136x over previous
#include <cuda_runtime.h>
#include <cuda_fp16.h>
#include <cstdint>

// Fixed problem shapes (SimpleGCN): N=50000 nodes, E=800000 edges,
// layers 256->256 (h1), 256->128 (h2), 128->128 (h3), out = [N, 512] fp32.
#define MAXN 50000
#define MAXE 800000
#define MPAD 50048

// ---------------- device scratch (static allocation; no cudaMalloc) --------
__device__ __half g_hh[(size_t)MPAD * 256];   // GEMM output, fp16
__device__ __half g_a16[(size_t)MPAD * 256];  // GEMM A input, fp16 (x16 / agg out)
__device__ __half g_w1h[256 * 256];           // W1^T fp16 [n][k]
__device__ __half g_w2h[128 * 256];           // W2^T fp16
__device__ __half g_w3h[128 * 128];           // W3^T fp16
__device__ float g_dinv[MAXN];
__device__ int   g_cnt[MAXN];     // INVARIANT: zero at call entry (restored by scatter)
__device__ int   g_offs[MAXN + 1];// exclusive scan of degrees; offs[n] = E
__device__ int   g_rank[MAXE];    // edge rank within its dst bucket (from count)
__device__ int   g_bsum[64];
__device__ int2  g_edge[MAXE];    // packed (src, norm-as-int) per edge

// ---------------- edge dtype probe (per-thread, no global flag) --------------
__device__ __forceinline__ bool probe64(const int* __restrict__ ei32) {
    int acc = 0;
#pragma unroll
    for (int i = 1; i < 32; i += 2) acc |= ei32[i];
    return acc == 0;
}
__device__ __forceinline__ int load_edge(const int* __restrict__ p32,
                                         const long long* __restrict__ p64,
                                         bool is64, int e, int n) {
    int v = is64 ? (int)p64[e] : p32[e];
    v = v < 0 ? 0 : (v >= n ? n - 1 : v);
    return v;
}

// ---------------- kernel 1: fused prep (count+rank || x->fp16 || W^T fp16) ---
__global__ void k_prep(const float* __restrict__ x,
                       const float* __restrict__ W1,
                       const float* __restrict__ W2,
                       const float* __restrict__ W3,
                       const int* __restrict__ ei32,
                       const long long* __restrict__ ei64, int E, int n) {
    const int CB = (E + 255) >> 8;
    const int XB = (MPAD * 32) >> 8;
    const int W1E = 256 * 256, W2E = 128 * 256, W3E = 128 * 128;
    const int b = blockIdx.x, t = threadIdx.x;

    if (b < CB) {                            // --- degree histogram + rank ---
        int e = b * 256 + t;
        if (e < E) {
            bool is64 = probe64(ei32);
            int d = load_edge(ei32, ei64, is64, E + e, n);
            g_rank[e] = atomicAdd(&g_cnt[d], 1);
        }
    } else if (b < CB + XB) {                // --- x -> fp16 (8 elems/thread) ---
        int i = (b - CB) * 256 + t;
        int row = i >> 5, q = i & 31;
        uint4 hv = make_uint4(0, 0, 0, 0);
        if (row < n) {
            const float* p = &x[(size_t)row * 256 + q * 8];
            float4 f0 = *(const float4*)p;
            float4 f1 = *(const float4*)(p + 4);
            __half2 p0 = __floats2half2_rn(f0.x, f0.y);
            __half2 p1 = __floats2half2_rn(f0.z, f0.w);
            __half2 p2 = __floats2half2_rn(f1.x, f1.y);
            __half2 p3 = __floats2half2_rn(f1.z, f1.w);
            hv.x = *(uint32_t*)&p0; hv.y = *(uint32_t*)&p1;
            hv.z = *(uint32_t*)&p2; hv.w = *(uint32_t*)&p3;
        }
        *(uint4*)&g_a16[(size_t)row * 256 + q * 8] = hv;
    } else {                                 // --- W^T fp16, 3 layers ---
        int i = (b - CB - XB) * 256 + t;
        const float* W; __half* dh; int K, N;
        if (i < W1E)             { W = W1; dh = g_w1h; K = 256; N = 256; }
        else if (i < W1E + W2E)  { i -= W1E; W = W2; dh = g_w2h; K = 256; N = 128; }
        else if (i < W1E + W2E + W3E) { i -= W1E + W2E; W = W3; dh = g_w3h; K = 128; N = 128; }
        else return;
        int nn = i / K, kk = i - nn * K;
        dh[i] = __float2half_rn(W[(size_t)kk * N + nn]);
    }
}

// ---------------- kernel 2: block scan of degrees + dinv ---------------------
__global__ void k_scan_dinv(int n) {
    __shared__ int ws[32];
    int i = blockIdx.x * 1024 + threadIdx.x;
    int v = (i < n) ? g_cnt[i] : 0;
    if (i < n) g_dinv[i] = rsqrtf((float)(v + 1));  // +1 self-loop

    int lane = threadIdx.x & 31, w = threadIdx.x >> 5;
    int xs = v;
#pragma unroll
    for (int d = 1; d < 32; d <<= 1) {
        int tt = __shfl_up_sync(0xFFFFFFFFu, xs, d);
        if (lane >= d) xs += tt;
    }
    if (lane == 31) ws[w] = xs;
    __syncthreads();
    if (w == 0) {
        int y = ws[lane];
#pragma unroll
        for (int d = 1; d < 32; d <<= 1) {
            int tt = __shfl_up_sync(0xFFFFFFFFu, y, d);
            if (lane >= d) y += tt;
        }
        ws[lane] = y;
    }
    __syncthreads();
    int ex = (w ? ws[w - 1] : 0) + xs - v;
    if (i < n) g_offs[i] = ex;
    if (threadIdx.x == 1023) g_bsum[blockIdx.x] = ws[31];
}

// ---------------- kernel 3: add block prefixes + terminator -------------------
__global__ void k_scan_add(int n, int E) {
    __shared__ int sv[64];
    __shared__ int pref;
    int t = threadIdx.x;
    if (t < 64) sv[t] = (t < blockIdx.x) ? g_bsum[t] : 0;
    __syncthreads();
    if (t == 0) {
        int s = 0;
#pragma unroll
        for (int j = 0; j < 64; j++) s += sv[j];
        pref = s;
    }
    __syncthreads();
    int i = blockIdx.x * 1024 + t;
    if (i < n) g_offs[i] += pref;
    if (blockIdx.x == 0 && t == 0) g_offs[n] = E;  // total = sum of degrees
}

// ---------------- kernel 4: atomic-free scatter (rank-based positions) -------
// pos = offs[dst] + rank[e]; g_offs is NOT modified (stays exclusive scan).
__global__ void k_scatter(const int* __restrict__ ei32,
                          const long long* __restrict__ ei64, int E, int n) {
    int i = blockIdx.x * blockDim.x + threadIdx.x;
    if (i < n) g_cnt[i] = 0;                 // invariant for next call
    int e0 = i * 2;
    if (e0 >= E) return;
    bool is64 = probe64(ei32);
    bool has1 = (e0 + 1) < E;

    int s0 = load_edge(ei32, ei64, is64, e0, n);
    int d0 = load_edge(ei32, ei64, is64, E + e0, n);
    int r0 = g_rank[e0];
    int s1 = 0, d1 = 0, r1 = 0;
    if (has1) {
        s1 = load_edge(ei32, ei64, is64, e0 + 1, n);
        d1 = load_edge(ei32, ei64, is64, E + e0 + 1, n);
        r1 = g_rank[e0 + 1];
    }
    int pos0 = g_offs[d0] + r0;
    float w0 = g_dinv[s0] * g_dinv[d0];
    if (pos0 >= 0 && pos0 < MAXE) g_edge[pos0] = make_int2(s0, __float_as_int(w0));
    if (has1) {
        int pos1 = g_offs[d1] + r1;
        float w1 = g_dinv[s1] * g_dinv[d1];
        if (pos1 >= 0 && pos1 < MAXE) g_edge[pos1] = make_int2(s1, __float_as_int(w1));
    }
}

// ---------------- fp16 1-term warp-MMA GEMM (cp.async pipelined) -------------
// C[M,N] = g_a16[M,*256] @ W[K,N]; W^T fp16 selected by layer (device-side).
// CTA tile 128x128, 8 warps (2M x 4N), warp tile 64x32 via m16n8k16.
#define ROWW 20
#define ARR_B  (128 * ROWW * 4)
#define BUF_B1 (ARR_B * 2)

__device__ __forceinline__ void mma_f16(float* c, uint32_t a0, uint32_t a1,
                                        uint32_t a2, uint32_t a3,
                                        uint32_t b0, uint32_t b1) {
    asm volatile(
        "mma.sync.aligned.m16n8k16.row.col.f32.f16.f16.f32 "
        "{%0,%1,%2,%3}, {%4,%5,%6,%7}, {%8,%9}, {%0,%1,%2,%3};"
        : "+f"(c[0]), "+f"(c[1]), "+f"(c[2]), "+f"(c[3])
        : "r"(a0), "r"(a1), "r"(a2), "r"(a3), "r"(b0), "r"(b1));
}
__device__ __forceinline__ void cp16(uint32_t dst, const void* src) {
    asm volatile("cp.async.cg.shared.global [%0], [%1], 16;"
                 :: "r"(dst), "l"(src));
}
__device__ __forceinline__ uint32_t smem_u32(const void* p) {
    uint32_t a;
    asm("{ .reg .u64 t; cvta.to.shared.u64 t, %1; cvt.u32.u64 %0, t; }"
        : "=r"(a) : "l"(p));
    return a;
}

__global__ void __launch_bounds__(256, 2)
k_gemm_f16(int layer, int M, int K, int N) {
    extern __shared__ char smem[];
    const uint32_t sbase = smem_u32(smem);
    const __half* A  = g_a16;               // device-side binding; lda = 256
    const __half* Bh = (layer == 0) ? g_w1h : (layer == 1) ? g_w2h : g_w3h;
    const int lda = 256;

    const int tid  = threadIdx.x;
    const int lane = tid & 31;
    const int wid  = tid >> 5;
    const int wm   = wid & 1;
    const int wn   = wid >> 1;
    const int bm   = blockIdx.x * 128;
    const int bn   = blockIdx.y * 128;

    const int l4 = lane >> 2;
    const int l2 = (lane & 3) * 2;

    float acc[4][4][4];
#pragma unroll
    for (int i = 0; i < 4; i++)
#pragma unroll
        for (int j = 0; j < 4; j++)
#pragma unroll
            for (int k = 0; k < 4; k++) acc[i][j][k] = 0.f;

    const int c0r = tid >> 2, c0q = tid & 3;
    const int nStages = K >> 5;

    // A rows bm..bm+127 may exceed M but stay < MPAD (g_a16 padded): safe.
    auto issue = [&](int st, int buf) {
        const int k0 = st << 5;
        const uint32_t db = sbase + buf * BUF_B1;
        const uint32_t w0 = (c0r * ROWW + c0q * 4) * 4;
        const uint32_t w1 = ((c0r + 64) * ROWW + c0q * 4) * 4;
        const size_t a0 = (size_t)(bm + c0r) * lda + k0 + c0q * 8;
        const size_t a1 = (size_t)(bm + c0r + 64) * lda + k0 + c0q * 8;
        cp16(db + w0, A + a0);
        cp16(db + w1, A + a1);
        const size_t g0 = (size_t)(bn + c0r) * K + k0 + c0q * 8;
        const size_t g1 = (size_t)(bn + c0r + 64) * K + k0 + c0q * 8;
        cp16(db + ARR_B + w0, Bh + g0);
        cp16(db + ARR_B + w1, Bh + g1);
        asm volatile("cp.async.commit_group;");
    };

    issue(0, 0);

    for (int st = 0; st < nStages; st++) {
        const int buf = st & 1;
        if (st + 1 < nStages) {
            issue(st + 1, buf ^ 1);
            asm volatile("cp.async.wait_group 1;");
        } else {
            asm volatile("cp.async.wait_group 0;");
        }
        __syncthreads();

        const uint32_t* sA  = (const uint32_t*)(smem + buf * BUF_B1);
        const uint32_t* sBh = (const uint32_t*)(smem + buf * BUF_B1 + ARR_B);

#pragma unroll
        for (int ks = 0; ks < 2; ks++) {
            const int kwb = ks * 8 + (lane & 3);
            uint32_t bh[4][2];
#pragma unroll
            for (int nt = 0; nt < 4; nt++) {
                int rw = (wn * 32 + nt * 8 + l4) * ROWW + kwb;
                bh[nt][0] = sBh[rw]; bh[nt][1] = sBh[rw + 4];
            }
#pragma unroll
            for (int mt = 0; mt < 4; mt++) {
                int r0 = (wm * 64 + mt * 16 + l4) * ROWW + kwb;
                int r1 = r0 + 8 * ROWW;
                uint32_t a0 = sA[r0], a1 = sA[r1];
                uint32_t a2 = sA[r0 + 4], a3 = sA[r1 + 4];
#pragma unroll
                for (int nt = 0; nt < 4; nt++)
                    mma_f16(acc[mt][nt], a0, a1, a2, a3, bh[nt][0], bh[nt][1]);
            }
        }
        __syncthreads();
    }

#pragma unroll
    for (int mt = 0; mt < 4; mt++) {
#pragma unroll
        for (int nt = 0; nt < 4; nt++) {
            int row = bm + wm * 64 + mt * 16 + l4;
            int col = bn + wn * 32 + nt * 8 + l2;
            if (row < M)
                *(__half2*)&g_hh[(size_t)row * N + col] =
                    __floats2half2_rn(acc[mt][nt][0], acc[mt][nt][1]);
            if (row + 8 < M)
                *(__half2*)&g_hh[(size_t)(row + 8) * N + col] =
                    __floats2half2_rn(acc[mt][nt][2], acc[mt][nt][3]);
        }
    }
}

// ---------------- aggregation (fp16 gathers, packed edges) -------------------
__device__ __forceinline__ void unpack8(uint4 v, float* f) {
    float2 a = __half22float2(*(__half2*)&v.x);
    float2 b = __half22float2(*(__half2*)&v.y);
    float2 c = __half22float2(*(__half2*)&v.z);
    float2 d = __half22float2(*(__half2*)&v.w);
    f[0] = a.x; f[1] = a.y; f[2] = b.x; f[3] = b.y;
    f[4] = c.x; f[5] = c.y; f[6] = d.x; f[7] = d.y;
}

// NPB nodes per block; OC/8 threads per node. W16: also write fp16 copy to g_a16.
// g_offs is exclusive scan with terminator: beg = offs[node], end = offs[node+1].
template <int OC, int NPB, bool W16>
__global__ void k_agg(const float* __restrict__ bias,
                      float* __restrict__ out, int ldo, int n) {
    int node = blockIdx.x * NPB + threadIdx.y;
    if (node >= n) return;
    const int colb = threadIdx.x * 8;

    float di = g_dinv[node];
    float s2 = di * di;

    float acc[8], f[8];
    uint4 hs = *(const uint4*)&g_hh[(size_t)node * OC + colb];
    unpack8(hs, f);
#pragma unroll
    for (int j = 0; j < 8; j++) acc[j] = f[j] * s2;

    int beg = g_offs[node];
    int end = g_offs[node + 1];
    int e = beg;
    for (; e + 1 < end; e += 2) {
        int2 ed0 = g_edge[e], ed1 = g_edge[e + 1];
        float w0 = __int_as_float(ed0.y), w1 = __int_as_float(ed1.y);
        uint4 v0 = *(const uint4*)&g_hh[(size_t)ed0.x * OC + colb];
        uint4 v1 = *(const uint4*)&g_hh[(size_t)ed1.x * OC + colb];
        float f0[8], f1[8];
        unpack8(v0, f0);
        unpack8(v1, f1);
#pragma unroll
        for (int j = 0; j < 8; j++) acc[j] += f0[j] * w0 + f1[j] * w1;
    }
    if (e < end) {
        int2 ed = g_edge[e];
        float w = __int_as_float(ed.y);
        uint4 v = *(const uint4*)&g_hh[(size_t)ed.x * OC + colb];
        unpack8(v, f);
#pragma unroll
        for (int j = 0; j < 8; j++) acc[j] += f[j] * w;
    }

    float4 b0 = *(const float4*)&bias[colb];
    float4 b1 = *(const float4*)&bias[colb + 4];
    float r[8];
    r[0] = fmaxf(acc[0] + b0.x, 0.f); r[1] = fmaxf(acc[1] + b0.y, 0.f);
    r[2] = fmaxf(acc[2] + b0.z, 0.f); r[3] = fmaxf(acc[3] + b0.w, 0.f);
    r[4] = fmaxf(acc[4] + b1.x, 0.f); r[5] = fmaxf(acc[5] + b1.y, 0.f);
    r[6] = fmaxf(acc[6] + b1.z, 0.f); r[7] = fmaxf(acc[7] + b1.w, 0.f);

    float* op = &out[(size_t)node * ldo + colb];
    *(float4*)op       = make_float4(r[0], r[1], r[2], r[3]);
    *(float4*)(op + 4) = make_float4(r[4], r[5], r[6], r[7]);

    if (W16) {
        uint4 hv;
        __half2 p0 = __floats2half2_rn(r[0], r[1]);
        __half2 p1 = __floats2half2_rn(r[2], r[3]);
        __half2 p2 = __floats2half2_rn(r[4], r[5]);
        __half2 p3 = __floats2half2_rn(r[6], r[7]);
        hv.x = *(uint32_t*)&p0; hv.y = *(uint32_t*)&p1;
        hv.z = *(uint32_t*)&p2; hv.w = *(uint32_t*)&p3;
        *(uint4*)&g_a16[(size_t)node * 256 + colb] = hv;
    }
}

// ---------------- host launcher ----------------------------------------------
extern "C" void kernel_launch(void* const* d_in, const int* in_sizes, int n_in,
                              void* d_out, int out_size) {
    const float* x  = (const float*)d_in[0];
    const int*       ei32 = (const int*)d_in[1];
    const long long* ei64 = (const long long*)d_in[1];
    const float* W1 = (const float*)d_in[2];
    const float* b1 = (const float*)d_in[3];
    const float* W2 = (const float*)d_in[4];
    const float* b2 = (const float*)d_in[5];
    const float* W3 = (const float*)d_in[6];
    const float* b3 = (const float*)d_in[7];
    float* out = (float*)d_out;

    int n = in_sizes[0] / 256;   // 50000
    int E = in_sizes[1] / 2;     // 800000

    const int SMEM1 = 2 * BUF_B1;  // 40960
    cudaFuncSetAttribute(k_gemm_f16,
                         cudaFuncAttributeMaxDynamicSharedMemorySize, SMEM1);

    const int CB = (E + 255) / 256;
    const int XB = (MPAD * 32) / 256;
    const int WB = (256 * 256 + 128 * 256 + 128 * 128 + 255) / 256;
    k_prep<<<CB + XB + WB, 256>>>(x, W1, W2, W3, ei32, ei64, E, n);

    int nb = (n + 1023) / 1024;  // 49
    k_scan_dinv<<<nb, 1024>>>(n);
    k_scan_add<<<nb, 1024>>>(n, E);
    k_scatter<<<(E / 2 + 255) / 256, 256>>>(ei32, ei64, E, n);

    const int mtiles = (n + 127) / 128;  // 391

    // --- layer 1: 256 -> 256 ---
    k_gemm_f16<<<dim3(mtiles, 2), 256, SMEM1>>>(0, n, 256, 256);
    k_agg<256, 8, true><<<(n + 7) / 8, dim3(32, 8)>>>(b1, out, 512, n);

    // --- layer 2: 256 -> 128 ---
    k_gemm_f16<<<dim3(mtiles, 1), 256, SMEM1>>>(1, n, 256, 128);
    k_agg<128, 16, true><<<(n + 15) / 16, dim3(16, 16)>>>(b2, out + 256, 512, n);

    // --- layer 3: 128 -> 128 ---
    k_gemm_f16<<<dim3(mtiles, 1), 256, SMEM1>>>(2, n, 128, 128);
    k_agg<128, 16, false><<<(n + 15) / 16, dim3(16, 16)>>>(b3, out + 384, 512, n);
}

// round 15
// speedup vs baseline: 1.1634x; 1.0132x over previous
#include <cuda_runtime.h>
#include <cuda_fp16.h>
#include <cstdint>

// Fixed problem shapes (SimpleGCN): N=50000 nodes, E=800000 edges,
// layers 256->256 (h1), 256->128 (h2), 128->128 (h3), out = [N, 512] fp32.
#define MAXN 50000
#define MAXE 800000
#define MPAD 50048

// ---------------- device scratch (static allocation; no cudaMalloc) --------
__device__ __half g_hh[(size_t)MPAD * 256];   // GEMM output, fp16
__device__ __half g_a16[(size_t)MPAD * 256];  // GEMM A input, fp16 (x16 / agg out)
__device__ __half g_w1h[256 * 256];           // W1^T fp16 [n][k]
__device__ __half g_w2h[128 * 256];           // W2^T fp16
__device__ __half g_w3h[128 * 128];           // W3^T fp16
__device__ float g_dinv[MAXN];
__device__ int   g_cnt[MAXN];     // INVARIANT: zero at call entry (restored by scatter)
__device__ int   g_offs[MAXN + 1];// exclusive scan of degrees; offs[n] = E
__device__ int   g_rank[MAXE];    // edge rank within its dst bucket (from count)
__device__ int   g_bsum[64];
__device__ int2  g_edge[MAXE];    // packed (src, norm-as-int) per edge

// ---------------- edge dtype probe (per-thread, no global flag) --------------
__device__ __forceinline__ bool probe64(const int* __restrict__ ei32) {
    int acc = 0;
#pragma unroll
    for (int i = 1; i < 32; i += 2) acc |= ei32[i];
    return acc == 0;
}
__device__ __forceinline__ int load_edge(const int* __restrict__ p32,
                                         const long long* __restrict__ p64,
                                         bool is64, int e, int n) {
    int v = is64 ? (int)p64[e] : p32[e];
    v = v < 0 ? 0 : (v >= n ? n - 1 : v);
    return v;
}

// ---------------- kernel 1: fused prep (count+rank || x->fp16 || W^T fp16) ---
__global__ void k_prep(const float* __restrict__ x,
                       const float* __restrict__ W1,
                       const float* __restrict__ W2,
                       const float* __restrict__ W3,
                       const int* __restrict__ ei32,
                       const long long* __restrict__ ei64, int E, int n) {
    const int CB = (E + 255) >> 8;
    const int XB = (MPAD * 32) >> 8;
    const int W1E = 256 * 256, W2E = 128 * 256, W3E = 128 * 128;
    const int b = blockIdx.x, t = threadIdx.x;

    if (b < CB) {                            // --- degree histogram + rank ---
        int e = b * 256 + t;
        if (e < E) {
            bool is64 = probe64(ei32);
            int d = load_edge(ei32, ei64, is64, E + e, n);
            g_rank[e] = atomicAdd(&g_cnt[d], 1);
        }
    } else if (b < CB + XB) {                // --- x -> fp16 (8 elems/thread) ---
        int i = (b - CB) * 256 + t;
        int row = i >> 5, q = i & 31;
        uint4 hv = make_uint4(0, 0, 0, 0);
        if (row < n) {
            const float* p = &x[(size_t)row * 256 + q * 8];
            float4 f0 = *(const float4*)p;
            float4 f1 = *(const float4*)(p + 4);
            __half2 p0 = __floats2half2_rn(f0.x, f0.y);
            __half2 p1 = __floats2half2_rn(f0.z, f0.w);
            __half2 p2 = __floats2half2_rn(f1.x, f1.y);
            __half2 p3 = __floats2half2_rn(f1.z, f1.w);
            hv.x = *(uint32_t*)&p0; hv.y = *(uint32_t*)&p1;
            hv.z = *(uint32_t*)&p2; hv.w = *(uint32_t*)&p3;
        }
        *(uint4*)&g_a16[(size_t)row * 256 + q * 8] = hv;
    } else {                                 // --- W^T fp16, 3 layers ---
        int i = (b - CB - XB) * 256 + t;
        const float* W; __half* dh; int K, N;
        if (i < W1E)             { W = W1; dh = g_w1h; K = 256; N = 256; }
        else if (i < W1E + W2E)  { i -= W1E; W = W2; dh = g_w2h; K = 256; N = 128; }
        else if (i < W1E + W2E + W3E) { i -= W1E + W2E; W = W3; dh = g_w3h; K = 128; N = 128; }
        else return;
        int nn = i / K, kk = i - nn * K;
        dh[i] = __float2half_rn(W[(size_t)kk * N + nn]);
    }
}

// ---------------- kernel 2: block scan of degrees + dinv ---------------------
__global__ void k_scan_dinv(int n) {
    __shared__ int ws[32];
    int i = blockIdx.x * 1024 + threadIdx.x;
    int v = (i < n) ? g_cnt[i] : 0;
    if (i < n) g_dinv[i] = rsqrtf((float)(v + 1));  // +1 self-loop

    int lane = threadIdx.x & 31, w = threadIdx.x >> 5;
    int xs = v;
#pragma unroll
    for (int d = 1; d < 32; d <<= 1) {
        int tt = __shfl_up_sync(0xFFFFFFFFu, xs, d);
        if (lane >= d) xs += tt;
    }
    if (lane == 31) ws[w] = xs;
    __syncthreads();
    if (w == 0) {
        int y = ws[lane];
#pragma unroll
        for (int d = 1; d < 32; d <<= 1) {
            int tt = __shfl_up_sync(0xFFFFFFFFu, y, d);
            if (lane >= d) y += tt;
        }
        ws[lane] = y;
    }
    __syncthreads();
    int ex = (w ? ws[w - 1] : 0) + xs - v;
    if (i < n) g_offs[i] = ex;
    if (threadIdx.x == 1023) g_bsum[blockIdx.x] = ws[31];
}

// ---------------- kernel 3: add block prefixes + terminator -------------------
__global__ void k_scan_add(int n, int E) {
    __shared__ int sv[64];
    __shared__ int pref;
    int t = threadIdx.x;
    if (t < 64) sv[t] = (t < blockIdx.x) ? g_bsum[t] : 0;
    __syncthreads();
    if (t == 0) {
        int s = 0;
#pragma unroll
        for (int j = 0; j < 64; j++) s += sv[j];
        pref = s;
    }
    __syncthreads();
    int i = blockIdx.x * 1024 + t;
    if (i < n) g_offs[i] += pref;
    if (blockIdx.x == 0 && t == 0) g_offs[n] = E;  // total = sum of degrees
}

// ---------------- kernel 4: atomic-free scatter, 4 edges/thread --------------
// pos = offs[dst] + rank[e]; g_offs is NOT modified (stays exclusive scan).
__global__ void k_scatter(const int* __restrict__ ei32,
                          const long long* __restrict__ ei64, int E, int n) {
    int i = blockIdx.x * blockDim.x + threadIdx.x;
    if (i < n) g_cnt[i] = 0;                 // invariant for next call
    int e0 = i * 4;
    if (e0 >= E) return;
    bool is64 = probe64(ei32);

    int s[4], d[4], r[4];
    int cnt = (E - e0) < 4 ? (E - e0) : 4;
#pragma unroll
    for (int j = 0; j < 4; j++) {
        if (j < cnt) {
            s[j] = load_edge(ei32, ei64, is64, e0 + j, n);
            d[j] = load_edge(ei32, ei64, is64, E + e0 + j, n);
            r[j] = g_rank[e0 + j];
        }
    }
#pragma unroll
    for (int j = 0; j < 4; j++) {
        if (j < cnt) {
            int pos = g_offs[d[j]] + r[j];
            float w = g_dinv[s[j]] * g_dinv[d[j]];
            if (pos >= 0 && pos < MAXE)
                g_edge[pos] = make_int2(s[j], __float_as_int(w));
        }
    }
}

// ---------------- fp16 1-term warp-MMA GEMM (cp.async, K-chunk 64) -----------
// C[M,N] = g_a16[M,*256] @ W[K,N]; W^T fp16 selected by layer (device-side).
// CTA tile 128x128, 8 warps (2M x 4N), warp tile 64x32 via m16n8k16.
#define ROWW 36                      // 64 fp16 = 32 words + 4 pad (conflict-free)
#define ARR_B  (128 * ROWW * 4)      // 18432 B per array
#define BUF_B1 (ARR_B * 2)           // A + B per buffer

__device__ __forceinline__ void mma_f16(float* c, uint32_t a0, uint32_t a1,
                                        uint32_t a2, uint32_t a3,
                                        uint32_t b0, uint32_t b1) {
    asm volatile(
        "mma.sync.aligned.m16n8k16.row.col.f32.f16.f16.f32 "
        "{%0,%1,%2,%3}, {%4,%5,%6,%7}, {%8,%9}, {%0,%1,%2,%3};"
        : "+f"(c[0]), "+f"(c[1]), "+f"(c[2]), "+f"(c[3])
        : "r"(a0), "r"(a1), "r"(a2), "r"(a3), "r"(b0), "r"(b1));
}
__device__ __forceinline__ void cp16(uint32_t dst, const void* src) {
    asm volatile("cp.async.cg.shared.global [%0], [%1], 16;"
                 :: "r"(dst), "l"(src));
}
__device__ __forceinline__ uint32_t smem_u32(const void* p) {
    uint32_t a;
    asm("{ .reg .u64 t; cvta.to.shared.u64 t, %1; cvt.u32.u64 %0, t; }"
        : "=r"(a) : "l"(p));
    return a;
}

__global__ void __launch_bounds__(256, 2)
k_gemm_f16(int layer, int M, int K, int N) {
    extern __shared__ char smem[];
    const uint32_t sbase = smem_u32(smem);
    const __half* A  = g_a16;               // device-side binding; lda = 256
    const __half* Bh = (layer == 0) ? g_w1h : (layer == 1) ? g_w2h : g_w3h;
    const int lda = 256;

    const int tid  = threadIdx.x;
    const int lane = tid & 31;
    const int wid  = tid >> 5;
    const int wm   = wid & 1;
    const int wn   = wid >> 1;
    const int bm   = blockIdx.x * 128;
    const int bn   = blockIdx.y * 128;

    const int l4 = lane >> 2;
    const int l2 = (lane & 3) * 2;

    float acc[4][4][4];
#pragma unroll
    for (int i = 0; i < 4; i++)
#pragma unroll
        for (int j = 0; j < 4; j++)
#pragma unroll
            for (int k = 0; k < 4; k++) acc[i][j][k] = 0.f;

    // staging roles: 1024 16B-chunks per array, 4 per thread
    // chunk c: row = c>>3 (0..127), q = c&7 (k-octet); this thread: rows
    // (tid>>3)+{0,32,64,96}, fixed q = tid&7.
    const int cr = tid >> 3, cq = tid & 7;
    const int nStages = K >> 6;              // 64 k per stage

    // A rows bm..bm+127 may exceed M but stay < MPAD (g_a16 padded): safe.
    auto issue = [&](int st, int buf) {
        const int k0 = st << 6;
        const uint32_t db = sbase + buf * BUF_B1;
#pragma unroll
        for (int j = 0; j < 4; j++) {
            const int row = cr + j * 32;
            const uint32_t w = (row * ROWW + cq * 4) * 4;
            cp16(db + w, A + (size_t)(bm + row) * lda + k0 + cq * 8);
            cp16(db + ARR_B + w, Bh + (size_t)(bn + row) * K + k0 + cq * 8);
        }
        asm volatile("cp.async.commit_group;");
    };

    issue(0, 0);

    for (int st = 0; st < nStages; st++) {
        const int buf = st & 1;
        if (st + 1 < nStages) {
            issue(st + 1, buf ^ 1);
            asm volatile("cp.async.wait_group 1;");
        } else {
            asm volatile("cp.async.wait_group 0;");
        }
        __syncthreads();

        const uint32_t* sA  = (const uint32_t*)(smem + buf * BUF_B1);
        const uint32_t* sBh = (const uint32_t*)(smem + buf * BUF_B1 + ARR_B);

#pragma unroll
        for (int ks = 0; ks < 4; ks++) {
            const int kwb = ks * 8 + (lane & 3);
            uint32_t bh[4][2];
#pragma unroll
            for (int nt = 0; nt < 4; nt++) {
                int rw = (wn * 32 + nt * 8 + l4) * ROWW + kwb;
                bh[nt][0] = sBh[rw]; bh[nt][1] = sBh[rw + 4];
            }
#pragma unroll
            for (int mt = 0; mt < 4; mt++) {
                int r0 = (wm * 64 + mt * 16 + l4) * ROWW + kwb;
                int r1 = r0 + 8 * ROWW;
                uint32_t a0 = sA[r0], a1 = sA[r1];
                uint32_t a2 = sA[r0 + 4], a3 = sA[r1 + 4];
#pragma unroll
                for (int nt = 0; nt < 4; nt++)
                    mma_f16(acc[mt][nt], a0, a1, a2, a3, bh[nt][0], bh[nt][1]);
            }
        }
        __syncthreads();
    }

#pragma unroll
    for (int mt = 0; mt < 4; mt++) {
#pragma unroll
        for (int nt = 0; nt < 4; nt++) {
            int row = bm + wm * 64 + mt * 16 + l4;
            int col = bn + wn * 32 + nt * 8 + l2;
            if (row < M)
                *(__half2*)&g_hh[(size_t)row * N + col] =
                    __floats2half2_rn(acc[mt][nt][0], acc[mt][nt][1]);
            if (row + 8 < M)
                *(__half2*)&g_hh[(size_t)(row + 8) * N + col] =
                    __floats2half2_rn(acc[mt][nt][2], acc[mt][nt][3]);
        }
    }
}

// ---------------- aggregation (fp16 gathers, packed edges) -------------------
__device__ __forceinline__ void unpack8(uint4 v, float* f) {
    float2 a = __half22float2(*(__half2*)&v.x);
    float2 b = __half22float2(*(__half2*)&v.y);
    float2 c = __half22float2(*(__half2*)&v.z);
    float2 d = __half22float2(*(__half2*)&v.w);
    f[0] = a.x; f[1] = a.y; f[2] = b.x; f[3] = b.y;
    f[4] = c.x; f[5] = c.y; f[6] = d.x; f[7] = d.y;
}

// NPB nodes per block; OC/8 threads per node. W16: also write fp16 copy to g_a16.
// g_offs is exclusive scan with terminator: beg = offs[node], end = offs[node+1].
template <int OC, int NPB, bool W16>
__global__ void k_agg(const float* __restrict__ bias,
                      float* __restrict__ out, int ldo, int n) {
    int node = blockIdx.x * NPB + threadIdx.y;
    if (node >= n) return;
    const int colb = threadIdx.x * 8;

    float di = g_dinv[node];
    float s2 = di * di;

    float acc[8], f[8];
    uint4 hs = *(const uint4*)&g_hh[(size_t)node * OC + colb];
    unpack8(hs, f);
#pragma unroll
    for (int j = 0; j < 8; j++) acc[j] = f[j] * s2;

    int beg = g_offs[node];
    int end = g_offs[node + 1];
    int e = beg;
    for (; e + 1 < end; e += 2) {
        int2 ed0 = g_edge[e], ed1 = g_edge[e + 1];
        float w0 = __int_as_float(ed0.y), w1 = __int_as_float(ed1.y);
        uint4 v0 = *(const uint4*)&g_hh[(size_t)ed0.x * OC + colb];
        uint4 v1 = *(const uint4*)&g_hh[(size_t)ed1.x * OC + colb];
        float f0[8], f1[8];
        unpack8(v0, f0);
        unpack8(v1, f1);
#pragma unroll
        for (int j = 0; j < 8; j++) acc[j] += f0[j] * w0 + f1[j] * w1;
    }
    if (e < end) {
        int2 ed = g_edge[e];
        float w = __int_as_float(ed.y);
        uint4 v = *(const uint4*)&g_hh[(size_t)ed.x * OC + colb];
        unpack8(v, f);
#pragma unroll
        for (int j = 0; j < 8; j++) acc[j] += f[j] * w;
    }

    float4 b0 = *(const float4*)&bias[colb];
    float4 b1 = *(const float4*)&bias[colb + 4];
    float r[8];
    r[0] = fmaxf(acc[0] + b0.x, 0.f); r[1] = fmaxf(acc[1] + b0.y, 0.f);
    r[2] = fmaxf(acc[2] + b0.z, 0.f); r[3] = fmaxf(acc[3] + b0.w, 0.f);
    r[4] = fmaxf(acc[4] + b1.x, 0.f); r[5] = fmaxf(acc[5] + b1.y, 0.f);
    r[6] = fmaxf(acc[6] + b1.z, 0.f); r[7] = fmaxf(acc[7] + b1.w, 0.f);

    float* op = &out[(size_t)node * ldo + colb];
    *(float4*)op       = make_float4(r[0], r[1], r[2], r[3]);
    *(float4*)(op + 4) = make_float4(r[4], r[5], r[6], r[7]);

    if (W16) {
        uint4 hv;
        __half2 p0 = __floats2half2_rn(r[0], r[1]);
        __half2 p1 = __floats2half2_rn(r[2], r[3]);
        __half2 p2 = __floats2half2_rn(r[4], r[5]);
        __half2 p3 = __floats2half2_rn(r[6], r[7]);
        hv.x = *(uint32_t*)&p0; hv.y = *(uint32_t*)&p1;
        hv.z = *(uint32_t*)&p2; hv.w = *(uint32_t*)&p3;
        *(uint4*)&g_a16[(size_t)node * 256 + colb] = hv;
    }
}

// ---------------- host launcher ----------------------------------------------
extern "C" void kernel_launch(void* const* d_in, const int* in_sizes, int n_in,
                              void* d_out, int out_size) {
    const float* x  = (const float*)d_in[0];
    const int*       ei32 = (const int*)d_in[1];
    const long long* ei64 = (const long long*)d_in[1];
    const float* W1 = (const float*)d_in[2];
    const float* b1 = (const float*)d_in[3];
    const float* W2 = (const float*)d_in[4];
    const float* b2 = (const float*)d_in[5];
    const float* W3 = (const float*)d_in[6];
    const float* b3 = (const float*)d_in[7];
    float* out = (float*)d_out;

    int n = in_sizes[0] / 256;   // 50000
    int E = in_sizes[1] / 2;     // 800000

    const int SMEM1 = 2 * BUF_B1;  // 73728
    cudaFuncSetAttribute(k_gemm_f16,
                         cudaFuncAttributeMaxDynamicSharedMemorySize, SMEM1);

    const int CB = (E + 255) / 256;
    const int XB = (MPAD * 32) / 256;
    const int WB = (256 * 256 + 128 * 256 + 128 * 128 + 255) / 256;
    k_prep<<<CB + XB + WB, 256>>>(x, W1, W2, W3, ei32, ei64, E, n);

    int nb = (n + 1023) / 1024;  // 49
    k_scan_dinv<<<nb, 1024>>>(n);
    k_scan_add<<<nb, 1024>>>(n, E);
    k_scatter<<<(E / 4 + 255) / 256, 256>>>(ei32, ei64, E, n);

    const int mtiles = (n + 127) / 128;  // 391

    // --- layer 1: 256 -> 256 ---
    k_gemm_f16<<<dim3(mtiles, 2), 256, SMEM1>>>(0, n, 256, 256);
    k_agg<256, 8, true><<<(n + 7) / 8, dim3(32, 8)>>>(b1, out, 512, n);

    // --- layer 2: 256 -> 128 ---
    k_gemm_f16<<<dim3(mtiles, 1), 256, SMEM1>>>(1, n, 256, 128);
    k_agg<128, 16, true><<<(n + 15) / 16, dim3(16, 16)>>>(b2, out + 256, 512, n);

    // --- layer 3: 128 -> 128 ---
    k_gemm_f16<<<dim3(mtiles, 1), 256, SMEM1>>>(2, n, 128, 128);
    k_agg<128, 16, false><<<(n + 15) / 16, dim3(16, 16)>>>(b3, out + 384, 512, n);
}

// round 16
// speedup vs baseline: 1.1977x; 1.0294x over previous
#include <cuda_runtime.h>
#include <cuda_fp16.h>
#include <cstdint>

// Fixed problem shapes (SimpleGCN): N=50000 nodes, E=800000 edges,
// layers 256->256 (h1), 256->128 (h2), 128->128 (h3), out = [N, 512] fp32.
#define MAXN 50000
#define MAXE 800000
#define MPAD 50048

// ---------------- device scratch (static allocation; no cudaMalloc) --------
__device__ __half g_hh[(size_t)MPAD * 256];   // GEMM output, fp16
__device__ __half g_a16[(size_t)MPAD * 256];  // GEMM A input, fp16 (x16 / agg out)
__device__ __half g_w1h[256 * 256];           // W1^T fp16 [n][k]
__device__ __half g_w2h[128 * 256];           // W2^T fp16
__device__ __half g_w3h[128 * 128];           // W3^T fp16
__device__ float g_dinv[MAXN];
__device__ int   g_cnt[MAXN];     // INVARIANT: zero at call entry (restored by scatter)
__device__ int   g_offs[MAXN + 1];// exclusive scan of degrees; offs[n] = E
__device__ int   g_rank[MAXE];    // edge rank within its dst bucket (from count)
__device__ int   g_bsum[64];
__device__ int2  g_edge[MAXE];    // packed (src, norm-as-int) per edge

// ---------------- edge dtype probe (per-thread, no global flag) --------------
__device__ __forceinline__ bool probe64(const int* __restrict__ ei32) {
    int acc = 0;
#pragma unroll
    for (int i = 1; i < 32; i += 2) acc |= ei32[i];
    return acc == 0;
}
__device__ __forceinline__ int load_edge(const int* __restrict__ p32,
                                         const long long* __restrict__ p64,
                                         bool is64, int e, int n) {
    int v = is64 ? (int)p64[e] : p32[e];
    v = v < 0 ? 0 : (v >= n ? n - 1 : v);
    return v;
}

// ---------------- kernel 1: fused prep (count+rank || x->fp16 || W^T fp16) ---
__global__ void k_prep(const float* __restrict__ x,
                       const float* __restrict__ W1,
                       const float* __restrict__ W2,
                       const float* __restrict__ W3,
                       const int* __restrict__ ei32,
                       const long long* __restrict__ ei64, int E, int n) {
    const int CB = (E + 255) >> 8;
    const int XB = (MPAD * 32) >> 8;
    const int W1E = 256 * 256, W2E = 128 * 256, W3E = 128 * 128;
    const int b = blockIdx.x, t = threadIdx.x;

    if (b < CB) {                            // --- degree histogram + rank ---
        int e = b * 256 + t;
        if (e < E) {
            bool is64 = probe64(ei32);
            int d = load_edge(ei32, ei64, is64, E + e, n);
            g_rank[e] = atomicAdd(&g_cnt[d], 1);
        }
    } else if (b < CB + XB) {                // --- x -> fp16 (8 elems/thread) ---
        int i = (b - CB) * 256 + t;
        int row = i >> 5, q = i & 31;
        uint4 hv = make_uint4(0, 0, 0, 0);
        if (row < n) {
            const float* p = &x[(size_t)row * 256 + q * 8];
            float4 f0 = *(const float4*)p;
            float4 f1 = *(const float4*)(p + 4);
            __half2 p0 = __floats2half2_rn(f0.x, f0.y);
            __half2 p1 = __floats2half2_rn(f0.z, f0.w);
            __half2 p2 = __floats2half2_rn(f1.x, f1.y);
            __half2 p3 = __floats2half2_rn(f1.z, f1.w);
            hv.x = *(uint32_t*)&p0; hv.y = *(uint32_t*)&p1;
            hv.z = *(uint32_t*)&p2; hv.w = *(uint32_t*)&p3;
        }
        *(uint4*)&g_a16[(size_t)row * 256 + q * 8] = hv;
    } else {                                 // --- W^T fp16, 3 layers ---
        int i = (b - CB - XB) * 256 + t;
        const float* W; __half* dh; int K, N;
        if (i < W1E)             { W = W1; dh = g_w1h; K = 256; N = 256; }
        else if (i < W1E + W2E)  { i -= W1E; W = W2; dh = g_w2h; K = 256; N = 128; }
        else if (i < W1E + W2E + W3E) { i -= W1E + W2E; W = W3; dh = g_w3h; K = 128; N = 128; }
        else return;
        int nn = i / K, kk = i - nn * K;
        dh[i] = __float2half_rn(W[(size_t)kk * N + nn]);
    }
}

// ---------------- kernel 2: block scan of degrees + dinv ---------------------
__global__ void k_scan_dinv(int n) {
    __shared__ int ws[32];
    int i = blockIdx.x * 1024 + threadIdx.x;
    int v = (i < n) ? g_cnt[i] : 0;
    if (i < n) g_dinv[i] = rsqrtf((float)(v + 1));  // +1 self-loop

    int lane = threadIdx.x & 31, w = threadIdx.x >> 5;
    int xs = v;
#pragma unroll
    for (int d = 1; d < 32; d <<= 1) {
        int tt = __shfl_up_sync(0xFFFFFFFFu, xs, d);
        if (lane >= d) xs += tt;
    }
    if (lane == 31) ws[w] = xs;
    __syncthreads();
    if (w == 0) {
        int y = ws[lane];
#pragma unroll
        for (int d = 1; d < 32; d <<= 1) {
            int tt = __shfl_up_sync(0xFFFFFFFFu, y, d);
            if (lane >= d) y += tt;
        }
        ws[lane] = y;
    }
    __syncthreads();
    int ex = (w ? ws[w - 1] : 0) + xs - v;
    if (i < n) g_offs[i] = ex;
    if (threadIdx.x == 1023) g_bsum[blockIdx.x] = ws[31];
}

// ---------------- kernel 3: add block prefixes + terminator -------------------
__global__ void k_scan_add(int n, int E) {
    __shared__ int sv[64];
    __shared__ int pref;
    int t = threadIdx.x;
    if (t < 64) sv[t] = (t < blockIdx.x) ? g_bsum[t] : 0;
    __syncthreads();
    if (t == 0) {
        int s = 0;
#pragma unroll
        for (int j = 0; j < 64; j++) s += sv[j];
        pref = s;
    }
    __syncthreads();
    int i = blockIdx.x * 1024 + t;
    if (i < n) g_offs[i] += pref;
    if (blockIdx.x == 0 && t == 0) g_offs[n] = E;  // total = sum of degrees
}

// ---------------- kernel 4: atomic-free scatter, 2 edges/thread --------------
// pos = offs[dst] + rank[e]; g_offs is NOT modified (stays exclusive scan).
__global__ void k_scatter(const int* __restrict__ ei32,
                          const long long* __restrict__ ei64, int E, int n) {
    int i = blockIdx.x * blockDim.x + threadIdx.x;
    if (i < n) g_cnt[i] = 0;                 // invariant for next call
    int e0 = i * 2;
    if (e0 >= E) return;
    bool is64 = probe64(ei32);
    bool has1 = (e0 + 1) < E;

    int s0 = load_edge(ei32, ei64, is64, e0, n);
    int d0 = load_edge(ei32, ei64, is64, E + e0, n);
    int r0 = g_rank[e0];
    int s1 = 0, d1 = 0, r1 = 0;
    if (has1) {
        s1 = load_edge(ei32, ei64, is64, e0 + 1, n);
        d1 = load_edge(ei32, ei64, is64, E + e0 + 1, n);
        r1 = g_rank[e0 + 1];
    }
    int pos0 = g_offs[d0] + r0;
    float w0 = g_dinv[s0] * g_dinv[d0];
    if (pos0 >= 0 && pos0 < MAXE) g_edge[pos0] = make_int2(s0, __float_as_int(w0));
    if (has1) {
        int pos1 = g_offs[d1] + r1;
        float w1 = g_dinv[s1] * g_dinv[d1];
        if (pos1 >= 0 && pos1 < MAXE) g_edge[pos1] = make_int2(s1, __float_as_int(w1));
    }
}

// ---------------- fp16 1-term warp-MMA GEMM (cp.async, K-chunk 64) -----------
// C[M,N] = g_a16[M,*256] @ W[K,N]; W^T fp16 selected by layer (device-side).
// CTA tile 128x128, 8 warps (2M x 4N), warp tile 64x32 via m16n8k16.
#define ROWW 36                      // 64 fp16 = 32 words + 4 pad (conflict-free)
#define ARR_B  (128 * ROWW * 4)      // 18432 B per array
#define BUF_B1 (ARR_B * 2)           // A + B per buffer

__device__ __forceinline__ void mma_f16(float* c, uint32_t a0, uint32_t a1,
                                        uint32_t a2, uint32_t a3,
                                        uint32_t b0, uint32_t b1) {
    asm volatile(
        "mma.sync.aligned.m16n8k16.row.col.f32.f16.f16.f32 "
        "{%0,%1,%2,%3}, {%4,%5,%6,%7}, {%8,%9}, {%0,%1,%2,%3};"
        : "+f"(c[0]), "+f"(c[1]), "+f"(c[2]), "+f"(c[3])
        : "r"(a0), "r"(a1), "r"(a2), "r"(a3), "r"(b0), "r"(b1));
}
__device__ __forceinline__ void cp16(uint32_t dst, const void* src) {
    asm volatile("cp.async.cg.shared.global [%0], [%1], 16;"
                 :: "r"(dst), "l"(src));
}
__device__ __forceinline__ uint32_t smem_u32(const void* p) {
    uint32_t a;
    asm("{ .reg .u64 t; cvta.to.shared.u64 t, %1; cvt.u32.u64 %0, t; }"
        : "=r"(a) : "l"(p));
    return a;
}

__global__ void __launch_bounds__(256, 2)
k_gemm_f16(int layer, int M, int K, int N) {
    extern __shared__ char smem[];
    const uint32_t sbase = smem_u32(smem);
    const __half* A  = g_a16;               // device-side binding; lda = 256
    const __half* Bh = (layer == 0) ? g_w1h : (layer == 1) ? g_w2h : g_w3h;
    const int lda = 256;

    const int tid  = threadIdx.x;
    const int lane = tid & 31;
    const int wid  = tid >> 5;
    const int wm   = wid & 1;
    const int wn   = wid >> 1;
    const int bm   = blockIdx.x * 128;
    const int bn   = blockIdx.y * 128;

    const int l4 = lane >> 2;
    const int l2 = (lane & 3) * 2;

    float acc[4][4][4];
#pragma unroll
    for (int i = 0; i < 4; i++)
#pragma unroll
        for (int j = 0; j < 4; j++)
#pragma unroll
            for (int k = 0; k < 4; k++) acc[i][j][k] = 0.f;

    const int cr = tid >> 3, cq = tid & 7;
    const int nStages = K >> 6;              // 64 k per stage

    // A rows bm..bm+127 may exceed M but stay < MPAD (g_a16 padded): safe.
    auto issue = [&](int st, int buf) {
        const int k0 = st << 6;
        const uint32_t db = sbase + buf * BUF_B1;
#pragma unroll
        for (int j = 0; j < 4; j++) {
            const int row = cr + j * 32;
            const uint32_t w = (row * ROWW + cq * 4) * 4;
            cp16(db + w, A + (size_t)(bm + row) * lda + k0 + cq * 8);
            cp16(db + ARR_B + w, Bh + (size_t)(bn + row) * K + k0 + cq * 8);
        }
        asm volatile("cp.async.commit_group;");
    };

    issue(0, 0);

    for (int st = 0; st < nStages; st++) {
        const int buf = st & 1;
        if (st + 1 < nStages) {
            issue(st + 1, buf ^ 1);
            asm volatile("cp.async.wait_group 1;");
        } else {
            asm volatile("cp.async.wait_group 0;");
        }
        __syncthreads();

        const uint32_t* sA  = (const uint32_t*)(smem + buf * BUF_B1);
        const uint32_t* sBh = (const uint32_t*)(smem + buf * BUF_B1 + ARR_B);

#pragma unroll
        for (int ks = 0; ks < 4; ks++) {
            const int kwb = ks * 8 + (lane & 3);
            uint32_t bh[4][2];
#pragma unroll
            for (int nt = 0; nt < 4; nt++) {
                int rw = (wn * 32 + nt * 8 + l4) * ROWW + kwb;
                bh[nt][0] = sBh[rw]; bh[nt][1] = sBh[rw + 4];
            }
#pragma unroll
            for (int mt = 0; mt < 4; mt++) {
                int r0 = (wm * 64 + mt * 16 + l4) * ROWW + kwb;
                int r1 = r0 + 8 * ROWW;
                uint32_t a0 = sA[r0], a1 = sA[r1];
                uint32_t a2 = sA[r0 + 4], a3 = sA[r1 + 4];
#pragma unroll
                for (int nt = 0; nt < 4; nt++)
                    mma_f16(acc[mt][nt], a0, a1, a2, a3, bh[nt][0], bh[nt][1]);
            }
        }
        __syncthreads();
    }

#pragma unroll
    for (int mt = 0; mt < 4; mt++) {
#pragma unroll
        for (int nt = 0; nt < 4; nt++) {
            int row = bm + wm * 64 + mt * 16 + l4;
            int col = bn + wn * 32 + nt * 8 + l2;
            if (row < M)
                *(__half2*)&g_hh[(size_t)row * N + col] =
                    __floats2half2_rn(acc[mt][nt][0], acc[mt][nt][1]);
            if (row + 8 < M)
                *(__half2*)&g_hh[(size_t)(row + 8) * N + col] =
                    __floats2half2_rn(acc[mt][nt][2], acc[mt][nt][3]);
        }
    }
}

// ---------------- aggregation (fp16 gathers, packed edges) -------------------
__device__ __forceinline__ void unpack8(uint4 v, float* f) {
    float2 a = __half22float2(*(__half2*)&v.x);
    float2 b = __half22float2(*(__half2*)&v.y);
    float2 c = __half22float2(*(__half2*)&v.z);
    float2 d = __half22float2(*(__half2*)&v.w);
    f[0] = a.x; f[1] = a.y; f[2] = b.x; f[3] = b.y;
    f[4] = c.x; f[5] = c.y; f[6] = d.x; f[7] = d.y;
}

// NPB nodes per block; OC/8 threads per node. W16: also write fp16 copy to g_a16.
// g_offs is exclusive scan with terminator: beg = offs[node], end = offs[node+1].
template <int OC, int NPB, bool W16>
__global__ void k_agg(const float* __restrict__ bias,
                      float* __restrict__ out, int ldo, int n) {
    int node = blockIdx.x * NPB + threadIdx.y;
    if (node >= n) return;
    const int colb = threadIdx.x * 8;

    float di = g_dinv[node];
    float s2 = di * di;

    float acc[8], f[8];
    uint4 hs = *(const uint4*)&g_hh[(size_t)node * OC + colb];
    unpack8(hs, f);
#pragma unroll
    for (int j = 0; j < 8; j++) acc[j] = f[j] * s2;

    int beg = g_offs[node];
    int end = g_offs[node + 1];
    int e = beg;
    for (; e + 1 < end; e += 2) {
        int2 ed0 = g_edge[e], ed1 = g_edge[e + 1];
        float w0 = __int_as_float(ed0.y), w1 = __int_as_float(ed1.y);
        uint4 v0 = *(const uint4*)&g_hh[(size_t)ed0.x * OC + colb];
        uint4 v1 = *(const uint4*)&g_hh[(size_t)ed1.x * OC + colb];
        float f0[8], f1[8];
        unpack8(v0, f0);
        unpack8(v1, f1);
#pragma unroll
        for (int j = 0; j < 8; j++) acc[j] += f0[j] * w0 + f1[j] * w1;
    }
    if (e < end) {
        int2 ed = g_edge[e];
        float w = __int_as_float(ed.y);
        uint4 v = *(const uint4*)&g_hh[(size_t)ed.x * OC + colb];
        unpack8(v, f);
#pragma unroll
        for (int j = 0; j < 8; j++) acc[j] += f[j] * w;
    }

    float4 b0 = *(const float4*)&bias[colb];
    float4 b1 = *(const float4*)&bias[colb + 4];
    float r[8];
    r[0] = fmaxf(acc[0] + b0.x, 0.f); r[1] = fmaxf(acc[1] + b0.y, 0.f);
    r[2] = fmaxf(acc[2] + b0.z, 0.f); r[3] = fmaxf(acc[3] + b0.w, 0.f);
    r[4] = fmaxf(acc[4] + b1.x, 0.f); r[5] = fmaxf(acc[5] + b1.y, 0.f);
    r[6] = fmaxf(acc[6] + b1.z, 0.f); r[7] = fmaxf(acc[7] + b1.w, 0.f);

    float* op = &out[(size_t)node * ldo + colb];
    *(float4*)op       = make_float4(r[0], r[1], r[2], r[3]);
    *(float4*)(op + 4) = make_float4(r[4], r[5], r[6], r[7]);

    if (W16) {
        uint4 hv;
        __half2 p0 = __floats2half2_rn(r[0], r[1]);
        __half2 p1 = __floats2half2_rn(r[2], r[3]);
        __half2 p2 = __floats2half2_rn(r[4], r[5]);
        __half2 p3 = __floats2half2_rn(r[6], r[7]);
        hv.x = *(uint32_t*)&p0; hv.y = *(uint32_t*)&p1;
        hv.z = *(uint32_t*)&p2; hv.w = *(uint32_t*)&p3;
        *(uint4*)&g_a16[(size_t)node * 256 + colb] = hv;
    }
}

// ---------------- host launcher ----------------------------------------------
extern "C" void kernel_launch(void* const* d_in, const int* in_sizes, int n_in,
                              void* d_out, int out_size) {
    const float* x  = (const float*)d_in[0];
    const int*       ei32 = (const int*)d_in[1];
    const long long* ei64 = (const long long*)d_in[1];
    const float* W1 = (const float*)d_in[2];
    const float* b1 = (const float*)d_in[3];
    const float* W2 = (const float*)d_in[4];
    const float* b2 = (const float*)d_in[5];
    const float* W3 = (const float*)d_in[6];
    const float* b3 = (const float*)d_in[7];
    float* out = (float*)d_out;

    int n = in_sizes[0] / 256;   // 50000
    int E = in_sizes[1] / 2;     // 800000

    const int SMEM1 = 2 * BUF_B1;  // 73728
    cudaFuncSetAttribute(k_gemm_f16,
                         cudaFuncAttributeMaxDynamicSharedMemorySize, SMEM1);

    // one-time side stream + events for the CSR/GEMM1 fork-join (created on
    // the uncaptured correctness call; reused by graph capture afterwards)
    static cudaStream_t s2 = nullptr;
    static cudaEvent_t evFork = nullptr, evJoin = nullptr;
    if (!s2) {
        cudaStreamCreateWithFlags(&s2, cudaStreamNonBlocking);
        cudaEventCreateWithFlags(&evFork, cudaEventDisableTiming);
        cudaEventCreateWithFlags(&evJoin, cudaEventDisableTiming);
    }

    const int CB = (E + 255) / 256;
    const int XB = (MPAD * 32) / 256;
    const int WB = (256 * 256 + 128 * 256 + 128 * 128 + 255) / 256;
    k_prep<<<CB + XB + WB, 256>>>(x, W1, W2, W3, ei32, ei64, E, n);

    // ---- fork: CSR branch (scan+scatter) on s2, GEMM1 on main stream ----
    cudaEventRecord(evFork, 0);
    cudaStreamWaitEvent(s2, evFork, 0);

    int nb = (n + 1023) / 1024;  // 49
    k_scan_dinv<<<nb, 1024, 0, s2>>>(n);
    k_scan_add<<<nb, 1024, 0, s2>>>(n, E);
    k_scatter<<<(E / 2 + 255) / 256, 256, 0, s2>>>(ei32, ei64, E, n);
    cudaEventRecord(evJoin, s2);

    const int mtiles = (n + 127) / 128;  // 391
    k_gemm_f16<<<dim3(mtiles, 2), 256, SMEM1>>>(0, n, 256, 256);

    // ---- join: agg1 needs GEMM1 + dinv + edges ----
    cudaStreamWaitEvent(0, evJoin, 0);
    k_agg<256, 8, true><<<(n + 7) / 8, dim3(32, 8)>>>(b1, out, 512, n);

    // --- layer 2: 256 -> 128 ---
    k_gemm_f16<<<dim3(mtiles, 1), 256, SMEM1>>>(1, n, 256, 128);
    k_agg<128, 16, true><<<(n + 15) / 16, dim3(16, 16)>>>(b2, out + 256, 512, n);

    // --- layer 3: 128 -> 128 ---
    k_gemm_f16<<<dim3(mtiles, 1), 256, SMEM1>>>(2, n, 128, 128);
    k_agg<128, 16, false><<<(n + 15) / 16, dim3(16, 16)>>>(b3, out + 384, 512, n);
}

// round 17
// speedup vs baseline: 1.2286x; 1.0258x over previous
#include <cuda_runtime.h>
#include <cuda_fp16.h>
#include <cstdint>

// Fixed problem shapes (SimpleGCN): N=50000 nodes, E=800000 edges,
// layers 256->256 (h1), 256->128 (h2), 128->128 (h3), out = [N, 512] fp32.
#define MAXN 50000
#define MAXE 800000
#define MPAD 50048

// ---------------- device scratch (static allocation; no cudaMalloc) --------
__device__ __half g_hh[(size_t)MPAD * 256];   // GEMM output, fp16
__device__ __half g_a16[(size_t)MPAD * 256];  // GEMM A input, fp16 (x16 / agg out)
__device__ __half g_w1h[256 * 256];           // W1^T fp16 [n][k]
__device__ __half g_w2h[128 * 256];           // W2^T fp16
__device__ __half g_w3h[128 * 128];           // W3^T fp16
__device__ float g_dinv[MAXN];
__device__ int   g_cnt[MAXN];     // INVARIANT: zero at call entry (restored by scatter)
__device__ int   g_offs[MAXN + 1];// exclusive scan of degrees; offs[n] = E
__device__ int   g_rank[MAXE];    // edge rank within its dst bucket (from count)
__device__ int   g_bsum[64];
__device__ int2  g_edge[MAXE];    // packed (src, norm-as-int) per edge

// ---------------- edge dtype probe (per-thread, no global flag) --------------
__device__ __forceinline__ bool probe64(const int* __restrict__ ei32) {
    int acc = 0;
#pragma unroll
    for (int i = 1; i < 32; i += 2) acc |= ei32[i];
    return acc == 0;
}
__device__ __forceinline__ int load_edge(const int* __restrict__ p32,
                                         const long long* __restrict__ p64,
                                         bool is64, int e, int n) {
    int v = is64 ? (int)p64[e] : p32[e];
    v = v < 0 ? 0 : (v >= n ? n - 1 : v);
    return v;
}

// ---------------- kernel 1a: degree histogram + rank (CSR critical path) -----
__global__ void k_prep_count(const int* __restrict__ ei32,
                             const long long* __restrict__ ei64, int E, int n) {
    int e = blockIdx.x * blockDim.x + threadIdx.x;
    if (e < E) {
        bool is64 = probe64(ei32);
        int d = load_edge(ei32, ei64, is64, E + e, n);
        g_rank[e] = atomicAdd(&g_cnt[d], 1);
    }
}

// ---------------- kernel 1b: streaming prep (x->fp16 || W^T fp16) ------------
__global__ void k_prep_stream(const float* __restrict__ x,
                              const float* __restrict__ W1,
                              const float* __restrict__ W2,
                              const float* __restrict__ W3, int n) {
    const int XB = (MPAD * 32) >> 8;
    const int W1E = 256 * 256, W2E = 128 * 256, W3E = 128 * 128;
    const int b = blockIdx.x, t = threadIdx.x;

    if (b < XB) {                            // --- x -> fp16 (8 elems/thread) ---
        int i = b * 256 + t;
        int row = i >> 5, q = i & 31;
        uint4 hv = make_uint4(0, 0, 0, 0);
        if (row < n) {
            const float* p = &x[(size_t)row * 256 + q * 8];
            float4 f0 = *(const float4*)p;
            float4 f1 = *(const float4*)(p + 4);
            __half2 p0 = __floats2half2_rn(f0.x, f0.y);
            __half2 p1 = __floats2half2_rn(f0.z, f0.w);
            __half2 p2 = __floats2half2_rn(f1.x, f1.y);
            __half2 p3 = __floats2half2_rn(f1.z, f1.w);
            hv.x = *(uint32_t*)&p0; hv.y = *(uint32_t*)&p1;
            hv.z = *(uint32_t*)&p2; hv.w = *(uint32_t*)&p3;
        }
        *(uint4*)&g_a16[(size_t)row * 256 + q * 8] = hv;
    } else {                                 // --- W^T fp16, 3 layers ---
        int i = (b - XB) * 256 + t;
        const float* W; __half* dh; int K, N;
        if (i < W1E)             { W = W1; dh = g_w1h; K = 256; N = 256; }
        else if (i < W1E + W2E)  { i -= W1E; W = W2; dh = g_w2h; K = 256; N = 128; }
        else if (i < W1E + W2E + W3E) { i -= W1E + W2E; W = W3; dh = g_w3h; K = 128; N = 128; }
        else return;
        int nn = i / K, kk = i - nn * K;
        dh[i] = __float2half_rn(W[(size_t)kk * N + nn]);
    }
}

// ---------------- kernel 2: block scan of degrees + dinv ---------------------
__global__ void k_scan_dinv(int n) {
    __shared__ int ws[32];
    int i = blockIdx.x * 1024 + threadIdx.x;
    int v = (i < n) ? g_cnt[i] : 0;
    if (i < n) g_dinv[i] = rsqrtf((float)(v + 1));  // +1 self-loop

    int lane = threadIdx.x & 31, w = threadIdx.x >> 5;
    int xs = v;
#pragma unroll
    for (int d = 1; d < 32; d <<= 1) {
        int tt = __shfl_up_sync(0xFFFFFFFFu, xs, d);
        if (lane >= d) xs += tt;
    }
    if (lane == 31) ws[w] = xs;
    __syncthreads();
    if (w == 0) {
        int y = ws[lane];
#pragma unroll
        for (int d = 1; d < 32; d <<= 1) {
            int tt = __shfl_up_sync(0xFFFFFFFFu, y, d);
            if (lane >= d) y += tt;
        }
        ws[lane] = y;
    }
    __syncthreads();
    int ex = (w ? ws[w - 1] : 0) + xs - v;
    if (i < n) g_offs[i] = ex;
    if (threadIdx.x == 1023) g_bsum[blockIdx.x] = ws[31];
}

// ---------------- kernel 3: add block prefixes + terminator -------------------
__global__ void k_scan_add(int n, int E) {
    __shared__ int sv[64];
    __shared__ int pref;
    int t = threadIdx.x;
    if (t < 64) sv[t] = (t < blockIdx.x) ? g_bsum[t] : 0;
    __syncthreads();
    if (t == 0) {
        int s = 0;
#pragma unroll
        for (int j = 0; j < 64; j++) s += sv[j];
        pref = s;
    }
    __syncthreads();
    int i = blockIdx.x * 1024 + t;
    if (i < n) g_offs[i] += pref;
    if (blockIdx.x == 0 && t == 0) g_offs[n] = E;  // total = sum of degrees
}

// ---------------- kernel 4: atomic-free scatter, 2 edges/thread --------------
// pos = offs[dst] + rank[e]; g_offs is NOT modified (stays exclusive scan).
__global__ void k_scatter(const int* __restrict__ ei32,
                          const long long* __restrict__ ei64, int E, int n) {
    int i = blockIdx.x * blockDim.x + threadIdx.x;
    if (i < n) g_cnt[i] = 0;                 // invariant for next call
    int e0 = i * 2;
    if (e0 >= E) return;
    bool is64 = probe64(ei32);
    bool has1 = (e0 + 1) < E;

    int s0 = load_edge(ei32, ei64, is64, e0, n);
    int d0 = load_edge(ei32, ei64, is64, E + e0, n);
    int r0 = g_rank[e0];
    int s1 = 0, d1 = 0, r1 = 0;
    if (has1) {
        s1 = load_edge(ei32, ei64, is64, e0 + 1, n);
        d1 = load_edge(ei32, ei64, is64, E + e0 + 1, n);
        r1 = g_rank[e0 + 1];
    }
    int pos0 = g_offs[d0] + r0;
    float w0 = g_dinv[s0] * g_dinv[d0];
    if (pos0 >= 0 && pos0 < MAXE) g_edge[pos0] = make_int2(s0, __float_as_int(w0));
    if (has1) {
        int pos1 = g_offs[d1] + r1;
        float w1 = g_dinv[s1] * g_dinv[d1];
        if (pos1 >= 0 && pos1 < MAXE) g_edge[pos1] = make_int2(s1, __float_as_int(w1));
    }
}

// ---------------- fp16 1-term warp-MMA GEMM (cp.async, K-chunk 64) -----------
// C[M,N] = g_a16[M,*256] @ W[K,N]; W^T fp16 selected by layer (device-side).
// CTA tile 128x128, 8 warps (2M x 4N), warp tile 64x32 via m16n8k16.
#define ROWW 36                      // 64 fp16 = 32 words + 4 pad (conflict-free)
#define ARR_B  (128 * ROWW * 4)      // 18432 B per array
#define BUF_B1 (ARR_B * 2)           // A + B per buffer

__device__ __forceinline__ void mma_f16(float* c, uint32_t a0, uint32_t a1,
                                        uint32_t a2, uint32_t a3,
                                        uint32_t b0, uint32_t b1) {
    asm volatile(
        "mma.sync.aligned.m16n8k16.row.col.f32.f16.f16.f32 "
        "{%0,%1,%2,%3}, {%4,%5,%6,%7}, {%8,%9}, {%0,%1,%2,%3};"
        : "+f"(c[0]), "+f"(c[1]), "+f"(c[2]), "+f"(c[3])
        : "r"(a0), "r"(a1), "r"(a2), "r"(a3), "r"(b0), "r"(b1));
}
__device__ __forceinline__ void cp16(uint32_t dst, const void* src) {
    asm volatile("cp.async.cg.shared.global [%0], [%1], 16;"
                 :: "r"(dst), "l"(src));
}
__device__ __forceinline__ uint32_t smem_u32(const void* p) {
    uint32_t a;
    asm("{ .reg .u64 t; cvta.to.shared.u64 t, %1; cvt.u32.u64 %0, t; }"
        : "=r"(a) : "l"(p));
    return a;
}

__global__ void __launch_bounds__(256, 2)
k_gemm_f16(int layer, int M, int K, int N) {
    extern __shared__ char smem[];
    const uint32_t sbase = smem_u32(smem);
    const __half* A  = g_a16;               // device-side binding; lda = 256
    const __half* Bh = (layer == 0) ? g_w1h : (layer == 1) ? g_w2h : g_w3h;
    const int lda = 256;

    const int tid  = threadIdx.x;
    const int lane = tid & 31;
    const int wid  = tid >> 5;
    const int wm   = wid & 1;
    const int wn   = wid >> 1;
    const int bm   = blockIdx.x * 128;
    const int bn   = blockIdx.y * 128;

    const int l4 = lane >> 2;
    const int l2 = (lane & 3) * 2;

    float acc[4][4][4];
#pragma unroll
    for (int i = 0; i < 4; i++)
#pragma unroll
        for (int j = 0; j < 4; j++)
#pragma unroll
            for (int k = 0; k < 4; k++) acc[i][j][k] = 0.f;

    const int cr = tid >> 3, cq = tid & 7;
    const int nStages = K >> 6;              // 64 k per stage

    // A rows bm..bm+127 may exceed M but stay < MPAD (g_a16 padded): safe.
    auto issue = [&](int st, int buf) {
        const int k0 = st << 6;
        const uint32_t db = sbase + buf * BUF_B1;
#pragma unroll
        for (int j = 0; j < 4; j++) {
            const int row = cr + j * 32;
            const uint32_t w = (row * ROWW + cq * 4) * 4;
            cp16(db + w, A + (size_t)(bm + row) * lda + k0 + cq * 8);
            cp16(db + ARR_B + w, Bh + (size_t)(bn + row) * K + k0 + cq * 8);
        }
        asm volatile("cp.async.commit_group;");
    };

    issue(0, 0);

    for (int st = 0; st < nStages; st++) {
        const int buf = st & 1;
        if (st + 1 < nStages) {
            issue(st + 1, buf ^ 1);
            asm volatile("cp.async.wait_group 1;");
        } else {
            asm volatile("cp.async.wait_group 0;");
        }
        __syncthreads();

        const uint32_t* sA  = (const uint32_t*)(smem + buf * BUF_B1);
        const uint32_t* sBh = (const uint32_t*)(smem + buf * BUF_B1 + ARR_B);

#pragma unroll
        for (int ks = 0; ks < 4; ks++) {
            const int kwb = ks * 8 + (lane & 3);
            uint32_t bh[4][2];
#pragma unroll
            for (int nt = 0; nt < 4; nt++) {
                int rw = (wn * 32 + nt * 8 + l4) * ROWW + kwb;
                bh[nt][0] = sBh[rw]; bh[nt][1] = sBh[rw + 4];
            }
#pragma unroll
            for (int mt = 0; mt < 4; mt++) {
                int r0 = (wm * 64 + mt * 16 + l4) * ROWW + kwb;
                int r1 = r0 + 8 * ROWW;
                uint32_t a0 = sA[r0], a1 = sA[r1];
                uint32_t a2 = sA[r0 + 4], a3 = sA[r1 + 4];
#pragma unroll
                for (int nt = 0; nt < 4; nt++)
                    mma_f16(acc[mt][nt], a0, a1, a2, a3, bh[nt][0], bh[nt][1]);
            }
        }
        __syncthreads();
    }

#pragma unroll
    for (int mt = 0; mt < 4; mt++) {
#pragma unroll
        for (int nt = 0; nt < 4; nt++) {
            int row = bm + wm * 64 + mt * 16 + l4;
            int col = bn + wn * 32 + nt * 8 + l2;
            if (row < M)
                *(__half2*)&g_hh[(size_t)row * N + col] =
                    __floats2half2_rn(acc[mt][nt][0], acc[mt][nt][1]);
            if (row + 8 < M)
                *(__half2*)&g_hh[(size_t)(row + 8) * N + col] =
                    __floats2half2_rn(acc[mt][nt][2], acc[mt][nt][3]);
        }
    }
}

// ---------------- aggregation (fp16 gathers, packed edges, unroll 4) ---------
__device__ __forceinline__ void unpack8(uint4 v, float* f) {
    float2 a = __half22float2(*(__half2*)&v.x);
    float2 b = __half22float2(*(__half2*)&v.y);
    float2 c = __half22float2(*(__half2*)&v.z);
    float2 d = __half22float2(*(__half2*)&v.w);
    f[0] = a.x; f[1] = a.y; f[2] = b.x; f[3] = b.y;
    f[4] = c.x; f[5] = c.y; f[6] = d.x; f[7] = d.y;
}

// NPB nodes per block; OC/8 threads per node. W16: also write fp16 copy to g_a16.
// g_offs is exclusive scan with terminator: beg = offs[node], end = offs[node+1].
template <int OC, int NPB, bool W16>
__global__ void k_agg(const float* __restrict__ bias,
                      float* __restrict__ out, int ldo, int n) {
    int node = blockIdx.x * NPB + threadIdx.y;
    if (node >= n) return;
    const int colb = threadIdx.x * 8;

    float di = g_dinv[node];
    float s2 = di * di;

    float acc[8], f[8];
    uint4 hs = *(const uint4*)&g_hh[(size_t)node * OC + colb];
    unpack8(hs, f);
#pragma unroll
    for (int j = 0; j < 8; j++) acc[j] = f[j] * s2;

    int beg = g_offs[node];
    int end = g_offs[node + 1];
    int e = beg;
    for (; e + 3 < end; e += 4) {
        int2 ed0 = g_edge[e],     ed1 = g_edge[e + 1];
        int2 ed2 = g_edge[e + 2], ed3 = g_edge[e + 3];
        uint4 v0 = *(const uint4*)&g_hh[(size_t)ed0.x * OC + colb];
        uint4 v1 = *(const uint4*)&g_hh[(size_t)ed1.x * OC + colb];
        uint4 v2 = *(const uint4*)&g_hh[(size_t)ed2.x * OC + colb];
        uint4 v3 = *(const uint4*)&g_hh[(size_t)ed3.x * OC + colb];
        float w0 = __int_as_float(ed0.y), w1 = __int_as_float(ed1.y);
        float w2 = __int_as_float(ed2.y), w3 = __int_as_float(ed3.y);
        float f0[8], f1[8], f2[8], f3[8];
        unpack8(v0, f0); unpack8(v1, f1);
        unpack8(v2, f2); unpack8(v3, f3);
#pragma unroll
        for (int j = 0; j < 8; j++)
            acc[j] += f0[j] * w0 + f1[j] * w1 + f2[j] * w2 + f3[j] * w3;
    }
    for (; e < end; e++) {
        int2 ed = g_edge[e];
        float w = __int_as_float(ed.y);
        uint4 v = *(const uint4*)&g_hh[(size_t)ed.x * OC + colb];
        unpack8(v, f);
#pragma unroll
        for (int j = 0; j < 8; j++) acc[j] += f[j] * w;
    }

    float4 b0 = *(const float4*)&bias[colb];
    float4 b1 = *(const float4*)&bias[colb + 4];
    float r[8];
    r[0] = fmaxf(acc[0] + b0.x, 0.f); r[1] = fmaxf(acc[1] + b0.y, 0.f);
    r[2] = fmaxf(acc[2] + b0.z, 0.f); r[3] = fmaxf(acc[3] + b0.w, 0.f);
    r[4] = fmaxf(acc[4] + b1.x, 0.f); r[5] = fmaxf(acc[5] + b1.y, 0.f);
    r[6] = fmaxf(acc[6] + b1.z, 0.f); r[7] = fmaxf(acc[7] + b1.w, 0.f);

    float* op = &out[(size_t)node * ldo + colb];
    *(float4*)op       = make_float4(r[0], r[1], r[2], r[3]);
    *(float4*)(op + 4) = make_float4(r[4], r[5], r[6], r[7]);

    if (W16) {
        uint4 hv;
        __half2 p0 = __floats2half2_rn(r[0], r[1]);
        __half2 p1 = __floats2half2_rn(r[2], r[3]);
        __half2 p2 = __floats2half2_rn(r[4], r[5]);
        __half2 p3 = __floats2half2_rn(r[6], r[7]);
        hv.x = *(uint32_t*)&p0; hv.y = *(uint32_t*)&p1;
        hv.z = *(uint32_t*)&p2; hv.w = *(uint32_t*)&p3;
        *(uint4*)&g_a16[(size_t)node * 256 + colb] = hv;
    }
}

// ---------------- host launcher ----------------------------------------------
extern "C" void kernel_launch(void* const* d_in, const int* in_sizes, int n_in,
                              void* d_out, int out_size) {
    const float* x  = (const float*)d_in[0];
    const int*       ei32 = (const int*)d_in[1];
    const long long* ei64 = (const long long*)d_in[1];
    const float* W1 = (const float*)d_in[2];
    const float* b1 = (const float*)d_in[3];
    const float* W2 = (const float*)d_in[4];
    const float* b2 = (const float*)d_in[5];
    const float* W3 = (const float*)d_in[6];
    const float* b3 = (const float*)d_in[7];
    float* out = (float*)d_out;

    int n = in_sizes[0] / 256;   // 50000
    int E = in_sizes[1] / 2;     // 800000

    const int SMEM1 = 2 * BUF_B1;  // 73728
    cudaFuncSetAttribute(k_gemm_f16,
                         cudaFuncAttributeMaxDynamicSharedMemorySize, SMEM1);

    // one-time side stream + events for the fork-join (created on the
    // uncaptured correctness call; reused by graph capture afterwards)
    static cudaStream_t s2 = nullptr;
    static cudaEvent_t evFork = nullptr, evJoin = nullptr;
    if (!s2) {
        cudaStreamCreateWithFlags(&s2, cudaStreamNonBlocking);
        cudaEventCreateWithFlags(&evFork, cudaEventDisableTiming);
        cudaEventCreateWithFlags(&evJoin, cudaEventDisableTiming);
    }

    const int CB = (E + 255) / 256;
    const int XB = (MPAD * 32) / 256;
    const int WB = (256 * 256 + 128 * 256 + 128 * 128 + 255) / 256;
    int nb = (n + 1023) / 1024;  // 49
    const int mtiles = (n + 127) / 128;  // 391

    // ---- fork at stream head: full CSR chain on s2, prep_stream+GEMM1 main --
    cudaEventRecord(evFork, 0);
    cudaStreamWaitEvent(s2, evFork, 0);

    k_prep_count<<<CB, 256, 0, s2>>>(ei32, ei64, E, n);
    k_scan_dinv<<<nb, 1024, 0, s2>>>(n);
    k_scan_add<<<nb, 1024, 0, s2>>>(n, E);
    k_scatter<<<(E / 2 + 255) / 256, 256, 0, s2>>>(ei32, ei64, E, n);
    cudaEventRecord(evJoin, s2);

    k_prep_stream<<<XB + WB, 256>>>(x, W1, W2, W3, n);
    k_gemm_f16<<<dim3(mtiles, 2), 256, SMEM1>>>(0, n, 256, 256);

    // ---- join: agg1 needs GEMM1 + dinv + edges ----
    cudaStreamWaitEvent(0, evJoin, 0);
    k_agg<256, 8, true><<<(n + 7) / 8, dim3(32, 8)>>>(b1, out, 512, n);

    // --- layer 2: 256 -> 128 ---
    k_gemm_f16<<<dim3(mtiles, 1), 256, SMEM1>>>(1, n, 256, 128);
    k_agg<128, 16, true><<<(n + 15) / 16, dim3(16, 16)>>>(b2, out + 256, 512, n);

    // --- layer 3: 128 -> 128 ---
    k_gemm_f16<<<dim3(mtiles, 1), 256, SMEM1>>>(2, n, 128, 128);
    k_agg<128, 16, false><<<(n + 15) / 16, dim3(16, 16)>>>(b3, out + 384, 512, n);
}